// round 1
// baseline (speedup 1.0000x reference)
#include <cuda_runtime.h>
#include <math.h>

// Problem constants
#define Bb 2
#define Ss 2048
#define Dd 1024
#define Hh 16
#define DK 64
#define Mm (Bb*Ss)   // 4096

// Scratch (device globals -- no allocations allowed)
__device__ float g_Q[Mm*Dd];
__device__ float g_K[Mm*Dd];
__device__ float g_V[Mm*Dd];
__device__ float g_C[Mm*Dd];

// ---------------------------------------------------------------------------
// Classic SGEMM: C[M,N] = A[M,K] @ W[N,K]^T + bias[N]
// 128x128 block tile, BK=8, 256 threads, 8x8 per-thread register tile.
// ---------------------------------------------------------------------------
__global__ __launch_bounds__(256) void sgemm_bias(
    const float* __restrict__ A, const float* __restrict__ W,
    const float* __restrict__ bias, float* __restrict__ C,
    int M, int N, int K)
{
    __shared__ float As[8][128];
    __shared__ float Ws[8][128];

    const int tid = threadIdx.x;
    const int m0 = blockIdx.y * 128;
    const int n0 = blockIdx.x * 128;

    const int loadRow = tid >> 1;        // 0..127
    const int loadK   = (tid & 1) * 4;   // 0 or 4

    const int tRow = tid / 16;           // 0..15
    const int tCol = tid % 16;           // 0..15

    float acc[8][8];
#pragma unroll
    for (int i = 0; i < 8; i++)
#pragma unroll
        for (int j = 0; j < 8; j++) acc[i][j] = 0.f;

    const float* Aload = A + (size_t)(m0 + loadRow) * K + loadK;
    const float* Wload = W + (size_t)(n0 + loadRow) * K + loadK;

    for (int k0 = 0; k0 < K; k0 += 8) {
        float4 a = *(const float4*)(Aload + k0);
        float4 w = *(const float4*)(Wload + k0);
        As[loadK+0][loadRow] = a.x; As[loadK+1][loadRow] = a.y;
        As[loadK+2][loadRow] = a.z; As[loadK+3][loadRow] = a.w;
        Ws[loadK+0][loadRow] = w.x; Ws[loadK+1][loadRow] = w.y;
        Ws[loadK+2][loadRow] = w.z; Ws[loadK+3][loadRow] = w.w;
        __syncthreads();

#pragma unroll
        for (int kk = 0; kk < 8; kk++) {
            float ra[8], rw[8];
#pragma unroll
            for (int i = 0; i < 8; i++) ra[i] = As[kk][tRow*8 + i];
#pragma unroll
            for (int j = 0; j < 8; j++) rw[j] = Ws[kk][tCol*8 + j];
#pragma unroll
            for (int i = 0; i < 8; i++)
#pragma unroll
                for (int j = 0; j < 8; j++)
                    acc[i][j] += ra[i] * rw[j];
        }
        __syncthreads();
    }

#pragma unroll
    for (int i = 0; i < 8; i++) {
        int m = m0 + tRow*8 + i;
        float4 o0, o1;
        o0.x = acc[i][0] + bias[n0 + tCol*8 + 0];
        o0.y = acc[i][1] + bias[n0 + tCol*8 + 1];
        o0.z = acc[i][2] + bias[n0 + tCol*8 + 2];
        o0.w = acc[i][3] + bias[n0 + tCol*8 + 3];
        o1.x = acc[i][4] + bias[n0 + tCol*8 + 4];
        o1.y = acc[i][5] + bias[n0 + tCol*8 + 5];
        o1.z = acc[i][6] + bias[n0 + tCol*8 + 6];
        o1.w = acc[i][7] + bias[n0 + tCol*8 + 7];
        *(float4*)(C + (size_t)m * N + n0 + tCol*8)     = o0;
        *(float4*)(C + (size_t)m * N + n0 + tCol*8 + 4) = o1;
    }
}

// ---------------------------------------------------------------------------
// Flash-style attention.
// Grid: (S/64, H, B). 256 threads (16x16). Each CTA: 64 q-rows of one head.
// Online softmax over 32 k-tiles of 64. smem padded to stride 65.
// ---------------------------------------------------------------------------
#define LDP 65
__global__ __launch_bounds__(256) void attn_kernel(
    const float* __restrict__ Qp, const float* __restrict__ Kp,
    const float* __restrict__ Vp, float* __restrict__ Cp,
    const float* __restrict__ posr, const int* __restrict__ mask)
{
    extern __shared__ float sm[];
    float* Qs   = sm;                 // 64*65
    float* Ks   = Qs  + 64*LDP;       // 64*65
    float* Vs   = Ks  + 64*LDP;       // 64*65
    float* Ps   = Vs  + 64*LDP;       // 64*65
    float* red  = Ps  + 64*LDP;       // 64*16
    float* mrow = red + 64*16;        // 64
    float* lrow = mrow + 64;          // 64
    float* fct  = lrow + 64;          // 64

    const int tid  = threadIdx.x;
    const int tRow = tid / 16;        // 0..15
    const int tCol = tid % 16;        // 0..15
    const int r0   = tRow * 4;
    const int c0   = tCol * 4;

    const int q0 = blockIdx.x * 64;
    const int h  = blockIdx.y;
    const int b  = blockIdx.z;

    const size_t headOff = (size_t)h * DK;
    const size_t rowBase = (size_t)b * Ss;   // row index base into [M, D]

    // Load Q tile (64 x 64), vectorized
#pragma unroll
    for (int t = 0; t < 4; t++) {
        int idx = tid + t * 256;          // 0..1023 float4 slots
        int row = idx >> 4;               // /16
        int c4  = (idx & 15) * 4;
        float4 v = *(const float4*)(Qp + (rowBase + q0 + row) * Dd + headOff + c4);
        Qs[row*LDP + c4 + 0] = v.x;
        Qs[row*LDP + c4 + 1] = v.y;
        Qs[row*LDP + c4 + 2] = v.z;
        Qs[row*LDP + c4 + 3] = v.w;
    }
    if (tid < 64) {
        mrow[tid] = -INFINITY;
        lrow[tid] = 0.f;
        fct[tid]  = 1.f;
    }
    __syncthreads();

    float acc[4][4];
#pragma unroll
    for (int i = 0; i < 4; i++)
#pragma unroll
        for (int j = 0; j < 4; j++) acc[i][j] = 0.f;

    for (int kt = 0; kt < Ss/64; kt++) {
        const int k0 = kt * 64;

        // Load K,V tiles
#pragma unroll
        for (int t = 0; t < 4; t++) {
            int idx = tid + t * 256;
            int row = idx >> 4;
            int c4  = (idx & 15) * 4;
            float4 kv = *(const float4*)(Kp + (rowBase + k0 + row) * Dd + headOff + c4);
            float4 vv = *(const float4*)(Vp + (rowBase + k0 + row) * Dd + headOff + c4);
            Ks[row*LDP + c4 + 0] = kv.x; Ks[row*LDP + c4 + 1] = kv.y;
            Ks[row*LDP + c4 + 2] = kv.z; Ks[row*LDP + c4 + 3] = kv.w;
            Vs[row*LDP + c4 + 0] = vv.x; Vs[row*LDP + c4 + 1] = vv.y;
            Vs[row*LDP + c4 + 2] = vv.z; Vs[row*LDP + c4 + 3] = vv.w;
        }
        __syncthreads();

        // S = Q @ K^T  (each thread 4x4)
        float s[4][4];
#pragma unroll
        for (int i = 0; i < 4; i++)
#pragma unroll
            for (int j = 0; j < 4; j++) s[i][j] = 0.f;

#pragma unroll 8
        for (int kk = 0; kk < 64; kk++) {
            float qr[4], kc[4];
#pragma unroll
            for (int i = 0; i < 4; i++) qr[i] = Qs[(r0+i)*LDP + kk];
#pragma unroll
            for (int j = 0; j < 4; j++) kc[j] = Ks[(c0+j)*LDP + kk];
#pragma unroll
            for (int i = 0; i < 4; i++)
#pragma unroll
                for (int j = 0; j < 4; j++)
                    s[i][j] += qr[i] * kc[j];
        }

        // scale + posr + mask
        const int kg = k0 + c0;
        bool mv[4];
#pragma unroll
        for (int j = 0; j < 4; j++) mv[j] = (mask[b*Ss + kg + j] != 0);
#pragma unroll
        for (int i = 0; i < 4; i++) {
            const float* pr = posr + ((size_t)b*Ss + (q0 + r0 + i)) * Ss + kg;
#pragma unroll
            for (int j = 0; j < 4; j++) {
                float val = s[i][j] * 0.125f + pr[j];
                s[i][j] = mv[j] ? val : -1.0e9f;
            }
        }

        // row max partials
#pragma unroll
        for (int i = 0; i < 4; i++) {
            float tm = fmaxf(fmaxf(s[i][0], s[i][1]), fmaxf(s[i][2], s[i][3]));
            red[(r0+i)*16 + tCol] = tm;
        }
        __syncthreads();

        if (tid < 64) {
            float mo = mrow[tid];
            float mt = red[tid*16];
#pragma unroll
            for (int t = 1; t < 16; t++) mt = fmaxf(mt, red[tid*16 + t]);
            float mn = fmaxf(mo, mt);
            float f  = __expf(mo - mn);
            mrow[tid] = mn;
            fct[tid]  = f;
            lrow[tid] *= f;
        }
        __syncthreads();

        // P = exp(S - m), stage to smem, rescale acc, partial row sums
#pragma unroll
        for (int i = 0; i < 4; i++) {
            float mr = mrow[r0 + i];
            float f  = fct[r0 + i];
            float ps = 0.f;
#pragma unroll
            for (int j = 0; j < 4; j++) {
                float e = __expf(s[i][j] - mr);
                Ps[(r0+i)*LDP + c0 + j] = e;
                ps += e;
                acc[i][j] *= f;
            }
            red[(r0+i)*16 + tCol] = ps;
        }
        __syncthreads();

        if (tid < 64) {
            float ls = 0.f;
#pragma unroll
            for (int t = 0; t < 16; t++) ls += red[tid*16 + t];
            lrow[tid] += ls;
        }

        // acc += P @ V   (output cols = c0..c0+3 of head dim)
#pragma unroll 8
        for (int c = 0; c < 64; c++) {
            float pv[4], vv[4];
#pragma unroll
            for (int i = 0; i < 4; i++) pv[i] = Ps[(r0+i)*LDP + c];
#pragma unroll
            for (int j = 0; j < 4; j++) vv[j] = Vs[c*LDP + c0 + j];
#pragma unroll
            for (int i = 0; i < 4; i++)
#pragma unroll
                for (int j = 0; j < 4; j++)
                    acc[i][j] += pv[i] * vv[j];
        }
        __syncthreads();
    }

    // normalize + write ctx (layout [b, q, h*DK + d])
#pragma unroll
    for (int i = 0; i < 4; i++) {
        float inv = 1.f / lrow[r0 + i];
        float* dst = Cp + (rowBase + q0 + r0 + i) * Dd + headOff + c0;
#pragma unroll
        for (int j = 0; j < 4; j++) dst[j] = acc[i][j] * inv;
    }
}

// ---------------------------------------------------------------------------
extern "C" void kernel_launch(void* const* d_in, const int* in_sizes, int n_in,
                              void* d_out, int out_size)
{
    const float* query = (const float*)d_in[0];
    const float* key   = (const float*)d_in[1];
    const float* value = (const float*)d_in[2];
    const int*   mask  = (const int*)  d_in[3];
    const float* posr  = (const float*)d_in[4];
    const float* Wq    = (const float*)d_in[5];
    const float* bq    = (const float*)d_in[6];
    const float* Wk    = (const float*)d_in[7];
    const float* bk    = (const float*)d_in[8];
    const float* Wv    = (const float*)d_in[9];
    const float* bv    = (const float*)d_in[10];
    const float* Wo    = (const float*)d_in[11];
    const float* bo    = (const float*)d_in[12];
    float* out = (float*)d_out;

    float *Qp, *Kp, *Vp, *Cp;
    cudaGetSymbolAddress((void**)&Qp, g_Q);
    cudaGetSymbolAddress((void**)&Kp, g_K);
    cudaGetSymbolAddress((void**)&Vp, g_V);
    cudaGetSymbolAddress((void**)&Cp, g_C);

    dim3 gGrid(Dd/128, Mm/128);   // (8, 32)
    sgemm_bias<<<gGrid, 256>>>(query, Wq, bq, Qp, Mm, Dd, Dd);
    sgemm_bias<<<gGrid, 256>>>(key,   Wk, bk, Kp, Mm, Dd, Dd);
    sgemm_bias<<<gGrid, 256>>>(value, Wv, bv, Vp, Mm, Dd, Dd);

    const int smemBytes = (4*64*LDP + 64*16 + 3*64) * sizeof(float);  // ~71.4 KB
    cudaFuncSetAttribute(attn_kernel, cudaFuncAttributeMaxDynamicSharedMemorySize, smemBytes);
    attn_kernel<<<dim3(Ss/64, Hh, Bb), 256, smemBytes>>>(Qp, Kp, Vp, Cp, posr, mask);

    sgemm_bias<<<gGrid, 256>>>(Cp, Wo, bo, out, Mm, Dd, Dd);
}

// round 4
// speedup vs baseline: 2.5253x; 2.5253x over previous
#include <cuda_runtime.h>
#include <cuda_bf16.h>
#include <math.h>
#include <stdint.h>

#define Bb 2
#define Ss 2048
#define Dd 1024
#define Hh 16
#define Mm 4096

// ---------------------------------------------------------------------------
// Scratch (device globals)
// ---------------------------------------------------------------------------
__device__ __nv_bfloat16 g_xqh[Mm*Dd], g_xql[Mm*Dd];
__device__ __nv_bfloat16 g_xkh[Mm*Dd], g_xkl[Mm*Dd];
__device__ __nv_bfloat16 g_xvh[Mm*Dd], g_xvl[Mm*Dd];
__device__ __nv_bfloat16 g_wqh[Dd*Dd], g_wql[Dd*Dd];
__device__ __nv_bfloat16 g_wkh[Dd*Dd], g_wkl[Dd*Dd];
__device__ __nv_bfloat16 g_wvh[Dd*Dd], g_wvl[Dd*Dd];
__device__ __nv_bfloat16 g_woh[Dd*Dd], g_wol[Dd*Dd];
__device__ __nv_bfloat16 g_qh[Mm*Dd],  g_ql[Mm*Dd];
__device__ __nv_bfloat16 g_kh[Mm*Dd],  g_kl[Mm*Dd];
__device__ __nv_bfloat16 g_vh[Mm*Dd],  g_vl[Mm*Dd];
__device__ __nv_bfloat16 g_ch[Mm*Dd],  g_cl[Mm*Dd];

// ---------------------------------------------------------------------------
// Helpers
// ---------------------------------------------------------------------------
__device__ __forceinline__ uint32_t smem_u32(const void* p) {
    return (uint32_t)__cvta_generic_to_shared(p);
}
__device__ __forceinline__ void cp16(uint32_t dst, const void* src) {
    asm volatile("cp.async.cg.shared.global [%0], [%1], 16;\n" :: "r"(dst), "l"(src));
}
#define CP_COMMIT() asm volatile("cp.async.commit_group;\n" ::: "memory")
template<int N> __device__ __forceinline__ void cp_wait() {
    asm volatile("cp.async.wait_group %0;\n" :: "n"(N) : "memory");
}
__device__ __forceinline__ void ldmx4(uint32_t& r0, uint32_t& r1, uint32_t& r2, uint32_t& r3, uint32_t a) {
    asm volatile("ldmatrix.sync.aligned.m8n8.x4.shared.b16 {%0,%1,%2,%3}, [%4];\n"
        : "=r"(r0), "=r"(r1), "=r"(r2), "=r"(r3) : "r"(a));
}
__device__ __forceinline__ void ldmx2t(uint32_t& r0, uint32_t& r1, uint32_t a) {
    asm volatile("ldmatrix.sync.aligned.m8n8.x2.trans.shared.b16 {%0,%1}, [%2];\n"
        : "=r"(r0), "=r"(r1) : "r"(a));
}
__device__ __forceinline__ void mma16816(float* c, uint32_t a0, uint32_t a1, uint32_t a2, uint32_t a3,
                                         uint32_t b0, uint32_t b1) {
    asm volatile("mma.sync.aligned.m16n8k16.row.col.f32.bf16.bf16.f32 "
        "{%0,%1,%2,%3}, {%4,%5,%6,%7}, {%8,%9}, {%0,%1,%2,%3};\n"
        : "+f"(c[0]), "+f"(c[1]), "+f"(c[2]), "+f"(c[3])
        : "r"(a0), "r"(a1), "r"(a2), "r"(a3), "r"(b0), "r"(b1));
}
// pack two f32 -> bf16x2 (e0 in low half)
__device__ __forceinline__ uint32_t pack_bf16(float e0, float e1) {
    union { __nv_bfloat162 v; uint32_t u; } t;
    t.v = __floats2bfloat162_rn(e0, e1);
    return t.u;
}
__device__ __forceinline__ float lof(uint32_t p) { return __uint_as_float(p << 16); }
__device__ __forceinline__ float hif(uint32_t p) { return __uint_as_float(p & 0xFFFF0000u); }

// exp on the FMA pipe (no MUFU)
__device__ __forceinline__ float fast_exp(float x) {
    x = fmaxf(x, -80.0f);
    float y  = x * 1.4426950408889634f;
    float rr = y + 12582912.0f;
    float n  = rr - 12582912.0f;
    float f  = y - n;
    float p  = 1.3333558e-3f;
    p = fmaf(p, f, 9.6181291e-3f);
    p = fmaf(p, f, 5.5504109e-2f);
    p = fmaf(p, f, 2.4022651e-1f);
    p = fmaf(p, f, 6.9314718e-1f);
    p = fmaf(p, f, 1.0f);
    int e = __float_as_int(rr) - 0x4B400000;
    float s = __int_as_float((e + 127) << 23);
    return p * s;
}

// swizzled smem byte offset within a tile of 128B rows (8 chunks of 16B)
__device__ __forceinline__ uint32_t swz(int row, int chunk) {
    return (uint32_t)(row * 128 + ((chunk ^ (row & 7)) << 4));
}

// ---------------------------------------------------------------------------
// pre_split: fp32 -> bf16 hi + bf16 residual lo, row-major
// ---------------------------------------------------------------------------
__global__ void pre_split(const float4* __restrict__ X, uint32_t* __restrict__ Xh,
                          uint32_t* __restrict__ Xl)
{
    int idx = blockIdx.x * 256 + threadIdx.x;
    float4 v = X[idx];
    uint32_t h0 = pack_bf16(v.x, v.y);
    uint32_t l0 = pack_bf16(v.x - lof(h0), v.y - hif(h0));
    uint32_t h1 = pack_bf16(v.z, v.w);
    uint32_t l1 = pack_bf16(v.z - lof(h1), v.w - hif(h1));
    Xh[idx*2]   = h0;  Xh[idx*2+1] = h1;
    Xl[idx*2]   = l0;  Xl[idx*2+1] = l1;
}

// ---------------------------------------------------------------------------
// bf16x3 GEMM: C[4096,1024] = A[4096,1024] @ W[1024,1024]^T + bias
// BM=128 BN=128 BK=64, 3-stage cp.async, 8 warps (2m x 4n), warp 64x32.
// ---------------------------------------------------------------------------
#define GST 65536                    // stage bytes: Ah|Al|Wh|Wl (16KB each)
#define GSMEM (3*GST)

__device__ __forceinline__ void gemm_load_stage(uint32_t base,
    const __nv_bfloat16* Ah, const __nv_bfloat16* Al,
    const __nv_bfloat16* Wh, const __nv_bfloat16* Wl,
    int m0, int n0, int k0, int tid)
{
#pragma unroll
    for (int i = 0; i < 4; i++) {
        int idx = tid + i * 256;          // 0..1023
        int r = idx >> 3, c = idx & 7;
        uint32_t so = swz(r, c);
        size_t ga = (size_t)(m0 + r) * Dd + k0 + c * 8;
        size_t gw = (size_t)(n0 + r) * Dd + k0 + c * 8;
        cp16(base + so,              Ah + ga);
        cp16(base + 16384 + so,      Al + ga);
        cp16(base + 32768 + so,      Wh + gw);
        cp16(base + 49152 + so,      Wl + gw);
    }
}

__global__ __launch_bounds__(256) void gemm_bf16x3(
    const __nv_bfloat16* __restrict__ Ah, const __nv_bfloat16* __restrict__ Al,
    const __nv_bfloat16* __restrict__ Wh, const __nv_bfloat16* __restrict__ Wl,
    const float* __restrict__ bias,
    float* __restrict__ Cf, uint32_t* __restrict__ Ch, uint32_t* __restrict__ Cl,
    int splitOut)
{
    extern __shared__ __align__(16) char sm[];
    const uint32_t smb = smem_u32(sm);
    const int tid = threadIdx.x, wid = tid >> 5, lane = tid & 31;
    const int m0 = blockIdx.y * 128, n0 = blockIdx.x * 128;
    const int wm = wid >> 2, wn = wid & 3;           // 2 x 4 warp grid
    const int sub = lane >> 3, lr = lane & 7;

    float acc[4][4][4];
#pragma unroll
    for (int a = 0; a < 4; a++)
#pragma unroll
        for (int b = 0; b < 4; b++)
#pragma unroll
            for (int c = 0; c < 4; c++) acc[a][b][c] = 0.f;

    gemm_load_stage(smb,       Ah, Al, Wh, Wl, m0, n0, 0,  tid); CP_COMMIT();
    gemm_load_stage(smb + GST, Ah, Al, Wh, Wl, m0, n0, 64, tid); CP_COMMIT();

    for (int it = 0; it < 16; it++) {
        if (it + 2 < 16) {
            gemm_load_stage(smb + ((it+2)%3)*GST, Ah, Al, Wh, Wl, m0, n0, (it+2)*64, tid);
            CP_COMMIT();
            cp_wait<2>();
        } else {
            cp_wait<0>();
        }
        __syncthreads();
        uint32_t stg = smb + (it%3)*GST;
        uint32_t Abase = stg, Albase = stg + 16384, Wbase = stg + 32768, Wlbase = stg + 49152;

#pragma unroll
        for (int ks = 0; ks < 4; ks++) {
            uint32_t ah[4][4], al[4][4];
#pragma unroll
            for (int mt = 0; mt < 4; mt++) {
                int row = wm*64 + mt*16 + lr + (sub & 1)*8;
                int ch  = 2*ks + (sub >> 1);
                uint32_t so = swz(row, ch);
                ldmx4(ah[mt][0], ah[mt][1], ah[mt][2], ah[mt][3], Abase + so);
                ldmx4(al[mt][0], al[mt][1], al[mt][2], al[mt][3], Albase + so);
            }
            uint32_t bh[8], bl[8];   // [nt pair: tiles 2p, 2p+1]
#pragma unroll
            for (int p = 0; p < 2; p++) {
                int row = wn*32 + p*16 + lr + (sub & 1)*8;
                int ch  = 2*ks + (sub >> 1);
                uint32_t so = swz(row, ch);
                ldmx4(bh[p*4+0], bh[p*4+1], bh[p*4+2], bh[p*4+3], Wbase + so);
                ldmx4(bl[p*4+0], bl[p*4+1], bl[p*4+2], bl[p*4+3], Wlbase + so);
            }
#pragma unroll
            for (int mt = 0; mt < 4; mt++) {
#pragma unroll
                for (int p = 0; p < 2; p++) {
                    // tile 2p: regs (0,2); tile 2p+1: regs (1,3)
                    mma16816(acc[mt][2*p],   ah[mt][0],ah[mt][1],ah[mt][2],ah[mt][3], bh[p*4+0], bh[p*4+2]);
                    mma16816(acc[mt][2*p],   ah[mt][0],ah[mt][1],ah[mt][2],ah[mt][3], bl[p*4+0], bl[p*4+2]);
                    mma16816(acc[mt][2*p],   al[mt][0],al[mt][1],al[mt][2],al[mt][3], bh[p*4+0], bh[p*4+2]);
                    mma16816(acc[mt][2*p+1], ah[mt][0],ah[mt][1],ah[mt][2],ah[mt][3], bh[p*4+1], bh[p*4+3]);
                    mma16816(acc[mt][2*p+1], ah[mt][0],ah[mt][1],ah[mt][2],ah[mt][3], bl[p*4+1], bl[p*4+3]);
                    mma16816(acc[mt][2*p+1], al[mt][0],al[mt][1],al[mt][2],al[mt][3], bh[p*4+1], bh[p*4+3]);
                }
            }
        }
        __syncthreads();
    }

    // Epilogue
#pragma unroll
    for (int mt = 0; mt < 4; mt++) {
#pragma unroll
        for (int nt = 0; nt < 4; nt++) {
            int gr = m0 + wm*64 + mt*16 + (lane >> 2);
            int gc = n0 + wn*32 + nt*8 + (lane & 3)*2;
            float b0 = bias[gc], b1 = bias[gc+1];
            float v0 = acc[mt][nt][0] + b0, v1 = acc[mt][nt][1] + b1;
            float v2 = acc[mt][nt][2] + b0, v3 = acc[mt][nt][3] + b1;
            if (splitOut) {
                uint32_t h0 = pack_bf16(v0, v1);
                uint32_t l0 = pack_bf16(v0 - lof(h0), v1 - hif(h0));
                uint32_t h1 = pack_bf16(v2, v3);
                uint32_t l1 = pack_bf16(v2 - lof(h1), v3 - hif(h1));
                Ch[(size_t)gr*512 + (gc>>1)]       = h0;
                Cl[(size_t)gr*512 + (gc>>1)]       = l0;
                Ch[(size_t)(gr+8)*512 + (gc>>1)]   = h1;
                Cl[(size_t)(gr+8)*512 + (gc>>1)]   = l1;
            } else {
                *(float2*)(Cf + (size_t)gr*Dd + gc)     = make_float2(v0, v1);
                *(float2*)(Cf + (size_t)(gr+8)*Dd + gc) = make_float2(v2, v3);
            }
        }
    }
}

// ---------------------------------------------------------------------------
// Flash attention, bf16x3 mma. CTA = 128 q-rows of one (b,h). 8 warps,
// warp w owns rows [w*16, w*16+16). K/V double-buffered. P in registers.
// ---------------------------------------------------------------------------
#define AQH 0
#define AQL 16384
#define AKV 32768              // stage: KH | KL(+8192) | VH(+16384) | VL(+24576)
#define AKVST 32768
#define ASMEM (AKV + 2*AKVST)  // 98304

__device__ __forceinline__ void attn_load_kv(uint32_t base,
    const __nv_bfloat16* Kh, const __nv_bfloat16* Kl,
    const __nv_bfloat16* Vh, const __nv_bfloat16* Vl,
    size_t rowBase, int headOff, int k0, int tid)
{
#pragma unroll
    for (int i = 0; i < 2; i++) {
        int idx = tid + i * 256;          // 0..511 : 64 rows x 8 chunks
        int r = idx >> 3, c = idx & 7;
        uint32_t so = swz(r, c);
        size_t g = (rowBase + k0 + r) * Dd + headOff + c * 8;
        cp16(base + so,         Kh + g);
        cp16(base + 8192 + so,  Kl + g);
        cp16(base + 16384 + so, Vh + g);
        cp16(base + 24576 + so, Vl + g);
    }
}

__global__ __launch_bounds__(256) void attn_kernel(
    const __nv_bfloat16* __restrict__ Qh, const __nv_bfloat16* __restrict__ Ql,
    const __nv_bfloat16* __restrict__ Kh, const __nv_bfloat16* __restrict__ Kl,
    const __nv_bfloat16* __restrict__ Vh, const __nv_bfloat16* __restrict__ Vl,
    uint32_t* __restrict__ Ch, uint32_t* __restrict__ Cl,
    const float* __restrict__ posr, const int* __restrict__ mask)
{
    extern __shared__ __align__(16) char sm[];
    const uint32_t smb = smem_u32(sm);
    const int tid = threadIdx.x, wid = tid >> 5, lane = tid & 31;
    const int sub = lane >> 3, lr = lane & 7;
    const int q0 = blockIdx.x * 128;
    const int h  = blockIdx.y;
    const int b  = blockIdx.z;
    const int headOff = h * 64;
    const size_t rowBase = (size_t)b * Ss;

    // load Q tile (128 x 64 hi+lo)
#pragma unroll
    for (int i = 0; i < 4; i++) {
        int idx = tid + i * 256;          // 0..1023
        int r = idx >> 3, c = idx & 7;
        uint32_t so = swz(r, c);
        size_t g = (rowBase + q0 + r) * Dd + headOff + c * 8;
        cp16(smb + AQH + so, Qh + g);
        cp16(smb + AQL + so, Ql + g);
    }
    attn_load_kv(smb + AKV, Kh, Kl, Vh, Vl, rowBase, headOff, 0, tid);
    CP_COMMIT();
    cp_wait<0>();
    __syncthreads();

    // preload Q fragments (warp-owned rows fixed)
    uint32_t qh[4][4], ql[4][4];
#pragma unroll
    for (int ks = 0; ks < 4; ks++) {
        int row = wid*16 + lr + (sub & 1)*8;
        int ch  = 2*ks + (sub >> 1);
        ldmx4(qh[ks][0], qh[ks][1], qh[ks][2], qh[ks][3], smb + AQH + swz(row, ch));
        ldmx4(ql[ks][0], ql[ks][1], ql[ks][2], ql[ks][3], smb + AQL + swz(row, ch));
    }

    float o[8][4];
#pragma unroll
    for (int i = 0; i < 8; i++)
#pragma unroll
        for (int j = 0; j < 4; j++) o[i][j] = 0.f;
    float mrow[2] = {-1e30f, -1e30f};
    float lrow[2] = {0.f, 0.f};

    const int r_lo = q0 + wid*16 + (lane >> 2);
    const int r_hi = r_lo + 8;

    for (int kt = 0; kt < 32; kt++) {
        uint32_t stg = smb + AKV + (kt & 1) * AKVST;
        if (kt + 1 < 32) {
            attn_load_kv(smb + AKV + ((kt+1) & 1) * AKVST, Kh, Kl, Vh, Vl,
                         rowBase, headOff, (kt+1)*64, tid);
            CP_COMMIT();
            cp_wait<1>();
        } else {
            cp_wait<0>();
        }
        __syncthreads();

        // ---- S = Q @ K^T (bf16x3) ----
        float s[8][4];
#pragma unroll
        for (int i = 0; i < 8; i++)
#pragma unroll
            for (int j = 0; j < 4; j++) s[i][j] = 0.f;

#pragma unroll
        for (int ks = 0; ks < 4; ks++) {
#pragma unroll
            for (int p = 0; p < 4; p++) {    // pairs of n-tiles (2p, 2p+1)
                int row = p*16 + lr + (sub & 1)*8;
                int ch  = 2*ks + (sub >> 1);
                uint32_t so = swz(row, ch);
                uint32_t kh4[4], kl4[4];
                ldmx4(kh4[0], kh4[1], kh4[2], kh4[3], stg + so);
                ldmx4(kl4[0], kl4[1], kl4[2], kl4[3], stg + 8192 + so);
                mma16816(s[2*p],   qh[ks][0],qh[ks][1],qh[ks][2],qh[ks][3], kh4[0], kh4[2]);
                mma16816(s[2*p],   qh[ks][0],qh[ks][1],qh[ks][2],qh[ks][3], kl4[0], kl4[2]);
                mma16816(s[2*p],   ql[ks][0],ql[ks][1],ql[ks][2],ql[ks][3], kh4[0], kh4[2]);
                mma16816(s[2*p+1], qh[ks][0],qh[ks][1],qh[ks][2],qh[ks][3], kh4[1], kh4[3]);
                mma16816(s[2*p+1], qh[ks][0],qh[ks][1],qh[ks][2],qh[ks][3], kl4[1], kl4[3]);
                mma16816(s[2*p+1], ql[ks][0],ql[ks][1],ql[ks][2],ql[ks][3], kh4[1], kh4[3]);
            }
        }

        // ---- scale + posr + mask ----
        const int colB = kt*64 + (lane & 3)*2;
#pragma unroll
        for (int nt = 0; nt < 8; nt++) {
            int col = colB + nt*8;
            int2 mk = *(const int2*)(mask + b*Ss + col);
            float2 p0 = *(const float2*)(posr + ((size_t)b*Ss + r_lo)*Ss + col);
            float2 p1 = *(const float2*)(posr + ((size_t)b*Ss + r_hi)*Ss + col);
            s[nt][0] = (mk.x != 0) ? fmaf(s[nt][0], 0.125f, p0.x) : -1e9f;
            s[nt][1] = (mk.y != 0) ? fmaf(s[nt][1], 0.125f, p0.y) : -1e9f;
            s[nt][2] = (mk.x != 0) ? fmaf(s[nt][2], 0.125f, p1.x) : -1e9f;
            s[nt][3] = (mk.y != 0) ? fmaf(s[nt][3], 0.125f, p1.y) : -1e9f;
        }

        // ---- online softmax (rows owned by quad; butterfly over lane%4) ----
        float tm0 = -1e30f, tm1 = -1e30f;
#pragma unroll
        for (int nt = 0; nt < 8; nt++) {
            tm0 = fmaxf(tm0, fmaxf(s[nt][0], s[nt][1]));
            tm1 = fmaxf(tm1, fmaxf(s[nt][2], s[nt][3]));
        }
        tm0 = fmaxf(tm0, __shfl_xor_sync(0xffffffffu, tm0, 1));
        tm0 = fmaxf(tm0, __shfl_xor_sync(0xffffffffu, tm0, 2));
        tm1 = fmaxf(tm1, __shfl_xor_sync(0xffffffffu, tm1, 1));
        tm1 = fmaxf(tm1, __shfl_xor_sync(0xffffffffu, tm1, 2));

        float mn0 = fmaxf(mrow[0], tm0), mn1 = fmaxf(mrow[1], tm1);
        float f0 = fast_exp(mrow[0] - mn0), f1 = fast_exp(mrow[1] - mn1);
        mrow[0] = mn0; mrow[1] = mn1;

        float sum0 = 0.f, sum1 = 0.f;
#pragma unroll
        for (int nt = 0; nt < 8; nt++) {
            s[nt][0] = fast_exp(s[nt][0] - mn0);
            s[nt][1] = fast_exp(s[nt][1] - mn0);
            s[nt][2] = fast_exp(s[nt][2] - mn1);
            s[nt][3] = fast_exp(s[nt][3] - mn1);
            sum0 += s[nt][0] + s[nt][1];
            sum1 += s[nt][2] + s[nt][3];
        }
        sum0 += __shfl_xor_sync(0xffffffffu, sum0, 1);
        sum0 += __shfl_xor_sync(0xffffffffu, sum0, 2);
        sum1 += __shfl_xor_sync(0xffffffffu, sum1, 1);
        sum1 += __shfl_xor_sync(0xffffffffu, sum1, 2);
        lrow[0] = lrow[0] * f0 + sum0;
        lrow[1] = lrow[1] * f1 + sum1;

#pragma unroll
        for (int nt2 = 0; nt2 < 8; nt2++) {
            o[nt2][0] *= f0; o[nt2][1] *= f0;
            o[nt2][2] *= f1; o[nt2][3] *= f1;
        }

        // ---- pack P (hi/lo) into A-frags; acc += P @ V ----
#pragma unroll
        for (int ks = 0; ks < 4; ks++) {
            int t0 = 2*ks, t1 = 2*ks + 1;
            uint32_t ph0 = pack_bf16(s[t0][0], s[t0][1]);
            uint32_t ph1 = pack_bf16(s[t0][2], s[t0][3]);
            uint32_t ph2 = pack_bf16(s[t1][0], s[t1][1]);
            uint32_t ph3 = pack_bf16(s[t1][2], s[t1][3]);
            uint32_t pl0 = pack_bf16(s[t0][0] - lof(ph0), s[t0][1] - hif(ph0));
            uint32_t pl1 = pack_bf16(s[t0][2] - lof(ph1), s[t0][3] - hif(ph1));
            uint32_t pl2 = pack_bf16(s[t1][0] - lof(ph2), s[t1][1] - hif(ph2));
            uint32_t pl3 = pack_bf16(s[t1][2] - lof(ph3), s[t1][3] - hif(ph3));
#pragma unroll
            for (int nt2 = 0; nt2 < 8; nt2++) {
                int row = ks*16 + (lane & 15);
                uint32_t soh = swz(row, nt2);
                uint32_t bvh0, bvh1, bvl0, bvl1;
                ldmx2t(bvh0, bvh1, stg + 16384 + soh);
                ldmx2t(bvl0, bvl1, stg + 24576 + soh);
                mma16816(o[nt2], ph0, ph1, ph2, ph3, bvh0, bvh1);
                mma16816(o[nt2], ph0, ph1, ph2, ph3, bvl0, bvl1);
                mma16816(o[nt2], pl0, pl1, pl2, pl3, bvh0, bvh1);
            }
        }
        __syncthreads();
    }

    // ---- epilogue: normalize, split hi/lo, write ctx ----
    float inv0 = 1.f / lrow[0], inv1 = 1.f / lrow[1];
    const size_t grLo = rowBase + (size_t)r_lo;
    const size_t grHi = rowBase + (size_t)r_hi;
#pragma unroll
    for (int nt2 = 0; nt2 < 8; nt2++) {
        int gc = headOff + nt2*8 + (lane & 3)*2;
        float v0 = o[nt2][0] * inv0, v1 = o[nt2][1] * inv0;
        float v2 = o[nt2][2] * inv1, v3 = o[nt2][3] * inv1;
        uint32_t h0 = pack_bf16(v0, v1);
        uint32_t l0 = pack_bf16(v0 - lof(h0), v1 - hif(h0));
        uint32_t h1 = pack_bf16(v2, v3);
        uint32_t l1 = pack_bf16(v2 - lof(h1), v3 - hif(h1));
        Ch[grLo*512 + (gc>>1)] = h0;
        Cl[grLo*512 + (gc>>1)] = l0;
        Ch[grHi*512 + (gc>>1)] = h1;
        Cl[grHi*512 + (gc>>1)] = l1;
    }
}

// ---------------------------------------------------------------------------
extern "C" void kernel_launch(void* const* d_in, const int* in_sizes, int n_in,
                              void* d_out, int out_size)
{
    const float* query = (const float*)d_in[0];
    const float* key   = (const float*)d_in[1];
    const float* value = (const float*)d_in[2];
    const int*   mask  = (const int*)  d_in[3];
    const float* posr  = (const float*)d_in[4];
    const float* Wq    = (const float*)d_in[5];
    const float* bq    = (const float*)d_in[6];
    const float* Wk    = (const float*)d_in[7];
    const float* bk    = (const float*)d_in[8];
    const float* Wv    = (const float*)d_in[9];
    const float* bv    = (const float*)d_in[10];
    const float* Wo    = (const float*)d_in[11];
    const float* bo    = (const float*)d_in[12];
    float* out = (float*)d_out;

    __nv_bfloat16 *xqh,*xql,*xkh,*xkl,*xvh,*xvl;
    __nv_bfloat16 *wqh,*wql,*wkh,*wkl,*wvh,*wvl,*woh,*wol;
    __nv_bfloat16 *qh,*ql,*kh,*kl,*vh,*vl,*ch,*cl;
    cudaGetSymbolAddress((void**)&xqh, g_xqh); cudaGetSymbolAddress((void**)&xql, g_xql);
    cudaGetSymbolAddress((void**)&xkh, g_xkh); cudaGetSymbolAddress((void**)&xkl, g_xkl);
    cudaGetSymbolAddress((void**)&xvh, g_xvh); cudaGetSymbolAddress((void**)&xvl, g_xvl);
    cudaGetSymbolAddress((void**)&wqh, g_wqh); cudaGetSymbolAddress((void**)&wql, g_wql);
    cudaGetSymbolAddress((void**)&wkh, g_wkh); cudaGetSymbolAddress((void**)&wkl, g_wkl);
    cudaGetSymbolAddress((void**)&wvh, g_wvh); cudaGetSymbolAddress((void**)&wvl, g_wvl);
    cudaGetSymbolAddress((void**)&woh, g_woh); cudaGetSymbolAddress((void**)&wol, g_wol);
    cudaGetSymbolAddress((void**)&qh, g_qh);   cudaGetSymbolAddress((void**)&ql, g_ql);
    cudaGetSymbolAddress((void**)&kh, g_kh);   cudaGetSymbolAddress((void**)&kl, g_kl);
    cudaGetSymbolAddress((void**)&vh, g_vh);   cudaGetSymbolAddress((void**)&vl, g_vl);
    cudaGetSymbolAddress((void**)&ch, g_ch);   cudaGetSymbolAddress((void**)&cl, g_cl);

    pre_split<<<Mm, 256>>>((const float4*)query, (uint32_t*)xqh, (uint32_t*)xql);
    pre_split<<<Mm, 256>>>((const float4*)key,   (uint32_t*)xkh, (uint32_t*)xkl);
    pre_split<<<Mm, 256>>>((const float4*)value, (uint32_t*)xvh, (uint32_t*)xvl);
    pre_split<<<Dd, 256>>>((const float4*)Wq, (uint32_t*)wqh, (uint32_t*)wql);
    pre_split<<<Dd, 256>>>((const float4*)Wk, (uint32_t*)wkh, (uint32_t*)wkl);
    pre_split<<<Dd, 256>>>((const float4*)Wv, (uint32_t*)wvh, (uint32_t*)wvl);
    pre_split<<<Dd, 256>>>((const float4*)Wo, (uint32_t*)woh, (uint32_t*)wol);

    cudaFuncSetAttribute(gemm_bf16x3, cudaFuncAttributeMaxDynamicSharedMemorySize, GSMEM);
    cudaFuncSetAttribute(attn_kernel, cudaFuncAttributeMaxDynamicSharedMemorySize, ASMEM);

    dim3 gGrid(Dd/128, Mm/128);   // (8, 32)
    gemm_bf16x3<<<gGrid, 256, GSMEM>>>(xqh, xql, wqh, wql, bq, nullptr, (uint32_t*)qh, (uint32_t*)ql, 1);
    gemm_bf16x3<<<gGrid, 256, GSMEM>>>(xkh, xkl, wkh, wkl, bk, nullptr, (uint32_t*)kh, (uint32_t*)kl, 1);
    gemm_bf16x3<<<gGrid, 256, GSMEM>>>(xvh, xvl, wvh, wvl, bv, nullptr, (uint32_t*)vh, (uint32_t*)vl, 1);

    attn_kernel<<<dim3(Ss/128, Hh, Bb), 256, ASMEM>>>(qh, ql, kh, kl, vh, vl,
        (uint32_t*)ch, (uint32_t*)cl, posr, mask);

    gemm_bf16x3<<<gGrid, 256, GSMEM>>>(ch, cl, woh, wol, bo, out, nullptr, nullptr, 0);
}

// round 5
// speedup vs baseline: 2.5986x; 1.0290x over previous
#include <cuda_runtime.h>
#include <cuda_bf16.h>
#include <math.h>
#include <stdint.h>

#define Bb 2
#define Ss 2048
#define Dd 1024
#define Hh 16
#define Mm 4096

// ---------------------------------------------------------------------------
// Scratch (device globals)
// ---------------------------------------------------------------------------
__device__ __nv_bfloat16 g_xqh[Mm*Dd], g_xql[Mm*Dd];
__device__ __nv_bfloat16 g_xkh[Mm*Dd], g_xkl[Mm*Dd];
__device__ __nv_bfloat16 g_xvh[Mm*Dd], g_xvl[Mm*Dd];
__device__ __nv_bfloat16 g_wqh[Dd*Dd], g_wql[Dd*Dd];
__device__ __nv_bfloat16 g_wkh[Dd*Dd], g_wkl[Dd*Dd];
__device__ __nv_bfloat16 g_wvh[Dd*Dd], g_wvl[Dd*Dd];
__device__ __nv_bfloat16 g_woh[Dd*Dd], g_wol[Dd*Dd];
__device__ __nv_bfloat16 g_qh[Mm*Dd],  g_ql[Mm*Dd];
__device__ __nv_bfloat16 g_kh[Mm*Dd],  g_kl[Mm*Dd];
__device__ __nv_bfloat16 g_vh[Mm*Dd],  g_vl[Mm*Dd];
__device__ __nv_bfloat16 g_ch[Mm*Dd],  g_cl[Mm*Dd];

// ---------------------------------------------------------------------------
// Helpers
// ---------------------------------------------------------------------------
__device__ __forceinline__ uint32_t smem_u32(const void* p) {
    return (uint32_t)__cvta_generic_to_shared(p);
}
__device__ __forceinline__ void cp16(uint32_t dst, const void* src) {
    asm volatile("cp.async.cg.shared.global [%0], [%1], 16;\n" :: "r"(dst), "l"(src));
}
#define CP_COMMIT() asm volatile("cp.async.commit_group;\n" ::: "memory")
template<int N> __device__ __forceinline__ void cp_wait() {
    asm volatile("cp.async.wait_group %0;\n" :: "n"(N) : "memory");
}
__device__ __forceinline__ void ldmx4(uint32_t& r0, uint32_t& r1, uint32_t& r2, uint32_t& r3, uint32_t a) {
    asm volatile("ldmatrix.sync.aligned.m8n8.x4.shared.b16 {%0,%1,%2,%3}, [%4];\n"
        : "=r"(r0), "=r"(r1), "=r"(r2), "=r"(r3) : "r"(a));
}
__device__ __forceinline__ void ldmx4t(uint32_t& r0, uint32_t& r1, uint32_t& r2, uint32_t& r3, uint32_t a) {
    asm volatile("ldmatrix.sync.aligned.m8n8.x4.trans.shared.b16 {%0,%1,%2,%3}, [%4];\n"
        : "=r"(r0), "=r"(r1), "=r"(r2), "=r"(r3) : "r"(a));
}
__device__ __forceinline__ void mma16816(float* c, uint32_t a0, uint32_t a1, uint32_t a2, uint32_t a3,
                                         uint32_t b0, uint32_t b1) {
    asm volatile("mma.sync.aligned.m16n8k16.row.col.f32.bf16.bf16.f32 "
        "{%0,%1,%2,%3}, {%4,%5,%6,%7}, {%8,%9}, {%0,%1,%2,%3};\n"
        : "+f"(c[0]), "+f"(c[1]), "+f"(c[2]), "+f"(c[3])
        : "r"(a0), "r"(a1), "r"(a2), "r"(a3), "r"(b0), "r"(b1));
}
// pack two f32 -> bf16x2 (e0 in low half)
__device__ __forceinline__ uint32_t pack_bf16(float e0, float e1) {
    union { __nv_bfloat162 v; uint32_t u; } t;
    t.v = __floats2bfloat162_rn(e0, e1);
    return t.u;
}
__device__ __forceinline__ float lof(uint32_t p) { return __uint_as_float(p << 16); }
__device__ __forceinline__ float hif(uint32_t p) { return __uint_as_float(p & 0xFFFF0000u); }

// exp on the FMA pipe (no MUFU)
__device__ __forceinline__ float fast_exp(float x) {
    x = fmaxf(x, -80.0f);
    float y  = x * 1.4426950408889634f;
    float rr = y + 12582912.0f;
    float n  = rr - 12582912.0f;
    float f  = y - n;
    float p  = 1.3333558e-3f;
    p = fmaf(p, f, 9.6181291e-3f);
    p = fmaf(p, f, 5.5504109e-2f);
    p = fmaf(p, f, 2.4022651e-1f);
    p = fmaf(p, f, 6.9314718e-1f);
    p = fmaf(p, f, 1.0f);
    int e = __float_as_int(rr) - 0x4B400000;
    float s = __int_as_float((e + 127) << 23);
    return p * s;
}

// swizzled smem byte offset within a tile of 128B rows (8 chunks of 16B)
__device__ __forceinline__ uint32_t swz(int row, int chunk) {
    return (uint32_t)(row * 128 + ((chunk ^ (row & 7)) << 4));
}

// ---------------------------------------------------------------------------
// pre_split: fp32 -> bf16 hi + bf16 residual lo, row-major. Fused variants.
// ---------------------------------------------------------------------------
__device__ __forceinline__ void split_one(const float4* __restrict__ X,
                                          uint32_t* __restrict__ Xh, uint32_t* __restrict__ Xl)
{
    int idx = blockIdx.x * 256 + threadIdx.x;
    float4 v = X[idx];
    uint32_t h0 = pack_bf16(v.x, v.y);
    uint32_t l0 = pack_bf16(v.x - lof(h0), v.y - hif(h0));
    uint32_t h1 = pack_bf16(v.z, v.w);
    uint32_t l1 = pack_bf16(v.z - lof(h1), v.w - hif(h1));
    Xh[idx*2]   = h0;  Xh[idx*2+1] = h1;
    Xl[idx*2]   = l0;  Xl[idx*2+1] = l1;
}

__global__ void pre_split3(const float4* __restrict__ A, const float4* __restrict__ B,
                           const float4* __restrict__ C,
                           uint32_t* __restrict__ Ah, uint32_t* __restrict__ Al,
                           uint32_t* __restrict__ Bh, uint32_t* __restrict__ Bl,
                           uint32_t* __restrict__ Ch, uint32_t* __restrict__ Cl)
{
    if (blockIdx.y == 0)      split_one(A, Ah, Al);
    else if (blockIdx.y == 1) split_one(B, Bh, Bl);
    else                      split_one(C, Ch, Cl);
}

__global__ void pre_split4(const float4* __restrict__ A, const float4* __restrict__ B,
                           const float4* __restrict__ C, const float4* __restrict__ D,
                           uint32_t* __restrict__ Ah, uint32_t* __restrict__ Al,
                           uint32_t* __restrict__ Bh, uint32_t* __restrict__ Bl,
                           uint32_t* __restrict__ Ch, uint32_t* __restrict__ Cl,
                           uint32_t* __restrict__ Dh, uint32_t* __restrict__ Dl)
{
    if (blockIdx.y == 0)      split_one(A, Ah, Al);
    else if (blockIdx.y == 1) split_one(B, Bh, Bl);
    else if (blockIdx.y == 2) split_one(C, Ch, Cl);
    else                      split_one(D, Dh, Dl);
}

// ---------------------------------------------------------------------------
// bf16x3 GEMM: C[4096,1024] = A[4096,1024] @ W[1024,1024]^T + bias
// BM=128 BN=128 BK=64, 3-stage cp.async, 8 warps (2m x 4n), warp 64x32.
// ---------------------------------------------------------------------------
#define GST 65536                    // stage bytes: Ah|Al|Wh|Wl (16KB each)
#define GSMEM (3*GST)

__device__ __forceinline__ void gemm_load_stage(uint32_t base,
    const __nv_bfloat16* Ah, const __nv_bfloat16* Al,
    const __nv_bfloat16* Wh, const __nv_bfloat16* Wl,
    int m0, int n0, int k0, int tid)
{
#pragma unroll
    for (int i = 0; i < 4; i++) {
        int idx = tid + i * 256;          // 0..1023
        int r = idx >> 3, c = idx & 7;
        uint32_t so = swz(r, c);
        size_t ga = (size_t)(m0 + r) * Dd + k0 + c * 8;
        size_t gw = (size_t)(n0 + r) * Dd + k0 + c * 8;
        cp16(base + so,              Ah + ga);
        cp16(base + 16384 + so,      Al + ga);
        cp16(base + 32768 + so,      Wh + gw);
        cp16(base + 49152 + so,      Wl + gw);
    }
}

__global__ __launch_bounds__(256) void gemm_bf16x3(
    const __nv_bfloat16* __restrict__ Ah, const __nv_bfloat16* __restrict__ Al,
    const __nv_bfloat16* __restrict__ Wh, const __nv_bfloat16* __restrict__ Wl,
    const float* __restrict__ bias,
    float* __restrict__ Cf, uint32_t* __restrict__ Ch, uint32_t* __restrict__ Cl,
    int splitOut)
{
    extern __shared__ __align__(16) char sm[];
    const uint32_t smb = smem_u32(sm);
    const int tid = threadIdx.x, wid = tid >> 5, lane = tid & 31;
    const int m0 = blockIdx.y * 128, n0 = blockIdx.x * 128;
    const int wm = wid >> 2, wn = wid & 3;           // 2 x 4 warp grid
    const int sub = lane >> 3, lr = lane & 7;

    float acc[4][4][4];
#pragma unroll
    for (int a = 0; a < 4; a++)
#pragma unroll
        for (int b = 0; b < 4; b++)
#pragma unroll
            for (int c = 0; c < 4; c++) acc[a][b][c] = 0.f;

    gemm_load_stage(smb,       Ah, Al, Wh, Wl, m0, n0, 0,  tid); CP_COMMIT();
    gemm_load_stage(smb + GST, Ah, Al, Wh, Wl, m0, n0, 64, tid); CP_COMMIT();

    for (int it = 0; it < 16; it++) {
        if (it + 2 < 16) {
            gemm_load_stage(smb + ((it+2)%3)*GST, Ah, Al, Wh, Wl, m0, n0, (it+2)*64, tid);
            CP_COMMIT();
            cp_wait<2>();
        } else {
            cp_wait<0>();
        }
        __syncthreads();
        uint32_t stg = smb + (it%3)*GST;
        uint32_t Abase = stg, Albase = stg + 16384, Wbase = stg + 32768, Wlbase = stg + 49152;

#pragma unroll
        for (int ks = 0; ks < 4; ks++) {
            uint32_t ah[4][4], al[4][4];
#pragma unroll
            for (int mt = 0; mt < 4; mt++) {
                int row = wm*64 + mt*16 + lr + (sub & 1)*8;
                int ch  = 2*ks + (sub >> 1);
                uint32_t so = swz(row, ch);
                ldmx4(ah[mt][0], ah[mt][1], ah[mt][2], ah[mt][3], Abase + so);
                ldmx4(al[mt][0], al[mt][1], al[mt][2], al[mt][3], Albase + so);
            }
            uint32_t bh[8], bl[8];   // [nt pair: tiles 2p, 2p+1]
#pragma unroll
            for (int p = 0; p < 2; p++) {
                int row = wn*32 + p*16 + lr + (sub & 1)*8;
                int ch  = 2*ks + (sub >> 1);
                uint32_t so = swz(row, ch);
                ldmx4(bh[p*4+0], bh[p*4+1], bh[p*4+2], bh[p*4+3], Wbase + so);
                ldmx4(bl[p*4+0], bl[p*4+1], bl[p*4+2], bl[p*4+3], Wlbase + so);
            }
#pragma unroll
            for (int mt = 0; mt < 4; mt++) {
#pragma unroll
                for (int p = 0; p < 2; p++) {
                    mma16816(acc[mt][2*p],   ah[mt][0],ah[mt][1],ah[mt][2],ah[mt][3], bh[p*4+0], bh[p*4+2]);
                    mma16816(acc[mt][2*p],   ah[mt][0],ah[mt][1],ah[mt][2],ah[mt][3], bl[p*4+0], bl[p*4+2]);
                    mma16816(acc[mt][2*p],   al[mt][0],al[mt][1],al[mt][2],al[mt][3], bh[p*4+0], bh[p*4+2]);
                    mma16816(acc[mt][2*p+1], ah[mt][0],ah[mt][1],ah[mt][2],ah[mt][3], bh[p*4+1], bh[p*4+3]);
                    mma16816(acc[mt][2*p+1], ah[mt][0],ah[mt][1],ah[mt][2],ah[mt][3], bl[p*4+1], bl[p*4+3]);
                    mma16816(acc[mt][2*p+1], al[mt][0],al[mt][1],al[mt][2],al[mt][3], bh[p*4+1], bh[p*4+3]);
                }
            }
        }
        __syncthreads();
    }

    // Epilogue
#pragma unroll
    for (int mt = 0; mt < 4; mt++) {
#pragma unroll
        for (int nt = 0; nt < 4; nt++) {
            int gr = m0 + wm*64 + mt*16 + (lane >> 2);
            int gc = n0 + wn*32 + nt*8 + (lane & 3)*2;
            float b0 = bias[gc], b1 = bias[gc+1];
            float v0 = acc[mt][nt][0] + b0, v1 = acc[mt][nt][1] + b1;
            float v2 = acc[mt][nt][2] + b0, v3 = acc[mt][nt][3] + b1;
            if (splitOut) {
                uint32_t h0 = pack_bf16(v0, v1);
                uint32_t l0 = pack_bf16(v0 - lof(h0), v1 - hif(h0));
                uint32_t h1 = pack_bf16(v2, v3);
                uint32_t l1 = pack_bf16(v2 - lof(h1), v3 - hif(h1));
                Ch[(size_t)gr*512 + (gc>>1)]       = h0;
                Cl[(size_t)gr*512 + (gc>>1)]       = l0;
                Ch[(size_t)(gr+8)*512 + (gc>>1)]   = h1;
                Cl[(size_t)(gr+8)*512 + (gc>>1)]   = l1;
            } else {
                *(float2*)(Cf + (size_t)gr*Dd + gc)     = make_float2(v0, v1);
                *(float2*)(Cf + (size_t)(gr+8)*Dd + gc) = make_float2(v2, v3);
            }
        }
    }
}

// ---------------------------------------------------------------------------
// Flash attention, bf16x3 mma. CTA = 128 q-rows of one (b,h). 8 warps,
// warp w owns rows [w*16, w*16+16). K/V double-buffered. P in registers.
// ---------------------------------------------------------------------------
#define AQH 0
#define AQL 16384
#define AKV 32768              // stage: KH | KL(+8192) | VH(+16384) | VL(+24576)
#define AKVST 32768
#define ASMEM (AKV + 2*AKVST)  // 98304

__device__ __forceinline__ void attn_load_kv(uint32_t base,
    const __nv_bfloat16* Kh, const __nv_bfloat16* Kl,
    const __nv_bfloat16* Vh, const __nv_bfloat16* Vl,
    size_t rowBase, int headOff, int k0, int tid)
{
#pragma unroll
    for (int i = 0; i < 2; i++) {
        int idx = tid + i * 256;          // 0..511 : 64 rows x 8 chunks
        int r = idx >> 3, c = idx & 7;
        uint32_t so = swz(r, c);
        size_t g = (rowBase + k0 + r) * Dd + headOff + c * 8;
        cp16(base + so,         Kh + g);
        cp16(base + 8192 + so,  Kl + g);
        cp16(base + 16384 + so, Vh + g);
        cp16(base + 24576 + so, Vl + g);
    }
}

__global__ __launch_bounds__(256, 2) void attn_kernel(
    const __nv_bfloat16* __restrict__ Qh, const __nv_bfloat16* __restrict__ Ql,
    const __nv_bfloat16* __restrict__ Kh, const __nv_bfloat16* __restrict__ Kl,
    const __nv_bfloat16* __restrict__ Vh, const __nv_bfloat16* __restrict__ Vl,
    uint32_t* __restrict__ Ch, uint32_t* __restrict__ Cl,
    const float* __restrict__ posr, const int* __restrict__ mask)
{
    extern __shared__ __align__(16) char sm[];
    const uint32_t smb = smem_u32(sm);
    const int tid = threadIdx.x, wid = tid >> 5, lane = tid & 31;
    const int sub = lane >> 3, lr = lane & 7;
    const int q0 = blockIdx.x * 128;
    const int h  = blockIdx.y;
    const int b  = blockIdx.z;
    const int headOff = h * 64;
    const size_t rowBase = (size_t)b * Ss;

    // load Q tile (128 x 64 hi+lo)
#pragma unroll
    for (int i = 0; i < 4; i++) {
        int idx = tid + i * 256;          // 0..1023
        int r = idx >> 3, c = idx & 7;
        uint32_t so = swz(r, c);
        size_t g = (rowBase + q0 + r) * Dd + headOff + c * 8;
        cp16(smb + AQH + so, Qh + g);
        cp16(smb + AQL + so, Ql + g);
    }
    attn_load_kv(smb + AKV, Kh, Kl, Vh, Vl, rowBase, headOff, 0, tid);
    CP_COMMIT();
    cp_wait<0>();
    __syncthreads();

    // preload Q fragments (warp-owned rows fixed)
    uint32_t qh[4][4], ql[4][4];
#pragma unroll
    for (int ks = 0; ks < 4; ks++) {
        int row = wid*16 + lr + (sub & 1)*8;
        int ch  = 2*ks + (sub >> 1);
        ldmx4(qh[ks][0], qh[ks][1], qh[ks][2], qh[ks][3], smb + AQH + swz(row, ch));
        ldmx4(ql[ks][0], ql[ks][1], ql[ks][2], ql[ks][3], smb + AQL + swz(row, ch));
    }

    float o[8][4];
#pragma unroll
    for (int i = 0; i < 8; i++)
#pragma unroll
        for (int j = 0; j < 4; j++) o[i][j] = 0.f;
    float mrow[2] = {-1e30f, -1e30f};
    float lrow[2] = {0.f, 0.f};

    const int r_lo = q0 + wid*16 + (lane >> 2);
    const int r_hi = r_lo + 8;
    const float* prLo = posr + ((size_t)b*Ss + r_lo)*Ss;
    const float* prHi = posr + ((size_t)b*Ss + r_hi)*Ss;
    const int*   mkB  = mask + b*Ss;

    for (int kt = 0; kt < 32; kt++) {
        uint32_t stg = smb + AKV + (kt & 1) * AKVST;
        if (kt + 1 < 32) {
            attn_load_kv(smb + AKV + ((kt+1) & 1) * AKVST, Kh, Kl, Vh, Vl,
                         rowBase, headOff, (kt+1)*64, tid);
            CP_COMMIT();
            cp_wait<1>();
        } else {
            cp_wait<0>();
        }
        __syncthreads();

        // ---- S = Q @ K^T (bf16x3) ----
        float s[8][4];
#pragma unroll
        for (int i = 0; i < 8; i++)
#pragma unroll
            for (int j = 0; j < 4; j++) s[i][j] = 0.f;

#pragma unroll
        for (int ks = 0; ks < 4; ks++) {
#pragma unroll
            for (int p = 0; p < 4; p++) {    // pairs of n-tiles (2p, 2p+1)
                int row = p*16 + lr + (sub & 1)*8;
                int ch  = 2*ks + (sub >> 1);
                uint32_t so = swz(row, ch);
                uint32_t kh4[4], kl4[4];
                ldmx4(kh4[0], kh4[1], kh4[2], kh4[3], stg + so);
                ldmx4(kl4[0], kl4[1], kl4[2], kl4[3], stg + 8192 + so);
                mma16816(s[2*p],   qh[ks][0],qh[ks][1],qh[ks][2],qh[ks][3], kh4[0], kh4[2]);
                mma16816(s[2*p],   qh[ks][0],qh[ks][1],qh[ks][2],qh[ks][3], kl4[0], kl4[2]);
                mma16816(s[2*p],   ql[ks][0],ql[ks][1],ql[ks][2],ql[ks][3], kh4[0], kh4[2]);
                mma16816(s[2*p+1], qh[ks][0],qh[ks][1],qh[ks][2],qh[ks][3], kh4[1], kh4[3]);
                mma16816(s[2*p+1], qh[ks][0],qh[ks][1],qh[ks][2],qh[ks][3], kl4[1], kl4[3]);
                mma16816(s[2*p+1], ql[ks][0],ql[ks][1],ql[ks][2],ql[ks][3], kh4[1], kh4[3]);
            }
        }

        // ---- scale + posr + mask ----
        const int colB = kt*64 + (lane & 3)*2;
#pragma unroll
        for (int nt = 0; nt < 8; nt++) {
            int col = colB + nt*8;
            int2 mk = *(const int2*)(mkB + col);
            float2 p0 = *(const float2*)(prLo + col);
            float2 p1 = *(const float2*)(prHi + col);
            s[nt][0] = (mk.x != 0) ? fmaf(s[nt][0], 0.125f, p0.x) : -1e9f;
            s[nt][1] = (mk.y != 0) ? fmaf(s[nt][1], 0.125f, p0.y) : -1e9f;
            s[nt][2] = (mk.x != 0) ? fmaf(s[nt][2], 0.125f, p1.x) : -1e9f;
            s[nt][3] = (mk.y != 0) ? fmaf(s[nt][3], 0.125f, p1.y) : -1e9f;
        }

        // ---- online softmax (rows owned by quad; butterfly over lane%4) ----
        float tm0 = -1e30f, tm1 = -1e30f;
#pragma unroll
        for (int nt = 0; nt < 8; nt++) {
            tm0 = fmaxf(tm0, fmaxf(s[nt][0], s[nt][1]));
            tm1 = fmaxf(tm1, fmaxf(s[nt][2], s[nt][3]));
        }
        tm0 = fmaxf(tm0, __shfl_xor_sync(0xffffffffu, tm0, 1));
        tm0 = fmaxf(tm0, __shfl_xor_sync(0xffffffffu, tm0, 2));
        tm1 = fmaxf(tm1, __shfl_xor_sync(0xffffffffu, tm1, 1));
        tm1 = fmaxf(tm1, __shfl_xor_sync(0xffffffffu, tm1, 2));

        float mn0 = fmaxf(mrow[0], tm0), mn1 = fmaxf(mrow[1], tm1);
        float f0 = fast_exp(mrow[0] - mn0), f1 = fast_exp(mrow[1] - mn1);
        mrow[0] = mn0; mrow[1] = mn1;

        float sum0 = 0.f, sum1 = 0.f;
#pragma unroll
        for (int nt = 0; nt < 8; nt++) {
            s[nt][0] = fast_exp(s[nt][0] - mn0);
            s[nt][1] = fast_exp(s[nt][1] - mn0);
            s[nt][2] = fast_exp(s[nt][2] - mn1);
            s[nt][3] = fast_exp(s[nt][3] - mn1);
            sum0 += s[nt][0] + s[nt][1];
            sum1 += s[nt][2] + s[nt][3];
        }
        sum0 += __shfl_xor_sync(0xffffffffu, sum0, 1);
        sum0 += __shfl_xor_sync(0xffffffffu, sum0, 2);
        sum1 += __shfl_xor_sync(0xffffffffu, sum1, 1);
        sum1 += __shfl_xor_sync(0xffffffffu, sum1, 2);
        lrow[0] = lrow[0] * f0 + sum0;
        lrow[1] = lrow[1] * f1 + sum1;

#pragma unroll
        for (int nt2 = 0; nt2 < 8; nt2++) {
            o[nt2][0] *= f0; o[nt2][1] *= f0;
            o[nt2][2] *= f1; o[nt2][3] *= f1;
        }

        // ---- pack P (hi/lo) into A-frags; acc += P @ V ----
#pragma unroll
        for (int ks = 0; ks < 4; ks++) {
            int t0 = 2*ks, t1 = 2*ks + 1;
            uint32_t ph0 = pack_bf16(s[t0][0], s[t0][1]);
            uint32_t ph1 = pack_bf16(s[t0][2], s[t0][3]);
            uint32_t ph2 = pack_bf16(s[t1][0], s[t1][1]);
            uint32_t ph3 = pack_bf16(s[t1][2], s[t1][3]);
            uint32_t pl0 = pack_bf16(s[t0][0] - lof(ph0), s[t0][1] - hif(ph0));
            uint32_t pl1 = pack_bf16(s[t0][2] - lof(ph1), s[t0][3] - hif(ph1));
            uint32_t pl2 = pack_bf16(s[t1][0] - lof(ph2), s[t1][1] - hif(ph2));
            uint32_t pl3 = pack_bf16(s[t1][2] - lof(ph3), s[t1][3] - hif(ph3));
            int row = ks*16 + (lane & 15);
#pragma unroll
            for (int np = 0; np < 4; np++) {   // pairs of d-tiles (2np, 2np+1)
                uint32_t so = swz(row, np*2 + (lane >> 4));
                uint32_t h0,h1,h2,h3, l0,l1,l2,l3;
                ldmx4t(h0,h1,h2,h3, stg + 16384 + so);
                ldmx4t(l0,l1,l2,l3, stg + 24576 + so);
                mma16816(o[2*np],   ph0,ph1,ph2,ph3, h0,h1);
                mma16816(o[2*np],   ph0,ph1,ph2,ph3, l0,l1);
                mma16816(o[2*np],   pl0,pl1,pl2,pl3, h0,h1);
                mma16816(o[2*np+1], ph0,ph1,ph2,ph3, h2,h3);
                mma16816(o[2*np+1], ph0,ph1,ph2,ph3, l2,l3);
                mma16816(o[2*np+1], pl0,pl1,pl2,pl3, h2,h3);
            }
        }
        __syncthreads();
    }

    // ---- epilogue: normalize, split hi/lo, write ctx ----
    float inv0 = 1.f / lrow[0], inv1 = 1.f / lrow[1];
    const size_t grLo = rowBase + (size_t)r_lo;
    const size_t grHi = rowBase + (size_t)r_hi;
#pragma unroll
    for (int nt2 = 0; nt2 < 8; nt2++) {
        int gc = headOff + nt2*8 + (lane & 3)*2;
        float v0 = o[nt2][0] * inv0, v1 = o[nt2][1] * inv0;
        float v2 = o[nt2][2] * inv1, v3 = o[nt2][3] * inv1;
        uint32_t h0 = pack_bf16(v0, v1);
        uint32_t l0 = pack_bf16(v0 - lof(h0), v1 - hif(h0));
        uint32_t h1 = pack_bf16(v2, v3);
        uint32_t l1 = pack_bf16(v2 - lof(h1), v3 - hif(h1));
        Ch[grLo*512 + (gc>>1)] = h0;
        Cl[grLo*512 + (gc>>1)] = l0;
        Ch[grHi*512 + (gc>>1)] = h1;
        Cl[grHi*512 + (gc>>1)] = l1;
    }
}

// ---------------------------------------------------------------------------
extern "C" void kernel_launch(void* const* d_in, const int* in_sizes, int n_in,
                              void* d_out, int out_size)
{
    const float* query = (const float*)d_in[0];
    const float* key   = (const float*)d_in[1];
    const float* value = (const float*)d_in[2];
    const int*   mask  = (const int*)  d_in[3];
    const float* posr  = (const float*)d_in[4];
    const float* Wq    = (const float*)d_in[5];
    const float* bq    = (const float*)d_in[6];
    const float* Wk    = (const float*)d_in[7];
    const float* bk    = (const float*)d_in[8];
    const float* Wv    = (const float*)d_in[9];
    const float* bv    = (const float*)d_in[10];
    const float* Wo    = (const float*)d_in[11];
    const float* bo    = (const float*)d_in[12];
    float* out = (float*)d_out;

    __nv_bfloat16 *xqh,*xql,*xkh,*xkl,*xvh,*xvl;
    __nv_bfloat16 *wqh,*wql,*wkh,*wkl,*wvh,*wvl,*woh,*wol;
    __nv_bfloat16 *qh,*ql,*kh,*kl,*vh,*vl,*ch,*cl;
    cudaGetSymbolAddress((void**)&xqh, g_xqh); cudaGetSymbolAddress((void**)&xql, g_xql);
    cudaGetSymbolAddress((void**)&xkh, g_xkh); cudaGetSymbolAddress((void**)&xkl, g_xkl);
    cudaGetSymbolAddress((void**)&xvh, g_xvh); cudaGetSymbolAddress((void**)&xvl, g_xvl);
    cudaGetSymbolAddress((void**)&wqh, g_wqh); cudaGetSymbolAddress((void**)&wql, g_wql);
    cudaGetSymbolAddress((void**)&wkh, g_wkh); cudaGetSymbolAddress((void**)&wkl, g_wkl);
    cudaGetSymbolAddress((void**)&wvh, g_wvh); cudaGetSymbolAddress((void**)&wvl, g_wvl);
    cudaGetSymbolAddress((void**)&woh, g_woh); cudaGetSymbolAddress((void**)&wol, g_wol);
    cudaGetSymbolAddress((void**)&qh, g_qh);   cudaGetSymbolAddress((void**)&ql, g_ql);
    cudaGetSymbolAddress((void**)&kh, g_kh);   cudaGetSymbolAddress((void**)&kl, g_kl);
    cudaGetSymbolAddress((void**)&vh, g_vh);   cudaGetSymbolAddress((void**)&vl, g_vl);
    cudaGetSymbolAddress((void**)&ch, g_ch);   cudaGetSymbolAddress((void**)&cl, g_cl);

    // launch #1, #2: fused tf-splits
    pre_split3<<<dim3(Mm, 3), 256>>>((const float4*)query, (const float4*)key, (const float4*)value,
        (uint32_t*)xqh, (uint32_t*)xql, (uint32_t*)xkh, (uint32_t*)xkl, (uint32_t*)xvh, (uint32_t*)xvl);
    pre_split4<<<dim3(Dd, 4), 256>>>((const float4*)Wq, (const float4*)Wk, (const float4*)Wv, (const float4*)Wo,
        (uint32_t*)wqh, (uint32_t*)wql, (uint32_t*)wkh, (uint32_t*)wkl,
        (uint32_t*)wvh, (uint32_t*)wvl, (uint32_t*)woh, (uint32_t*)wol);

    cudaFuncSetAttribute(gemm_bf16x3, cudaFuncAttributeMaxDynamicSharedMemorySize, GSMEM);
    cudaFuncSetAttribute(attn_kernel, cudaFuncAttributeMaxDynamicSharedMemorySize, ASMEM);

    dim3 gGrid(Dd/128, Mm/128);   // (8, 32)
    // launches #3-#5
    gemm_bf16x3<<<gGrid, 256, GSMEM>>>(xqh, xql, wqh, wql, bq, nullptr, (uint32_t*)qh, (uint32_t*)ql, 1);
    gemm_bf16x3<<<gGrid, 256, GSMEM>>>(xkh, xkl, wkh, wkl, bk, nullptr, (uint32_t*)kh, (uint32_t*)kl, 1);
    gemm_bf16x3<<<gGrid, 256, GSMEM>>>(xvh, xvl, wvh, wvl, bv, nullptr, (uint32_t*)vh, (uint32_t*)vl, 1);

    // launch #6 (ncu -s 5 -c 1 captures this one)
    attn_kernel<<<dim3(Ss/128, Hh, Bb), 256, ASMEM>>>(qh, ql, kh, kl, vh, vl,
        (uint32_t*)ch, (uint32_t*)cl, posr, mask);

    // launch #7
    gemm_bf16x3<<<gGrid, 256, GSMEM>>>(ch, cl, woh, wol, bo, out, nullptr, nullptr, 0);
}

// round 6
// speedup vs baseline: 2.6347x; 1.0139x over previous
#include <cuda_runtime.h>
#include <cuda_bf16.h>
#include <math.h>
#include <stdint.h>

#define Bb 2
#define Ss 2048
#define Dd 1024
#define Hh 16
#define Mm 4096

// ---------------------------------------------------------------------------
// Scratch (device globals)
// ---------------------------------------------------------------------------
__device__ __nv_bfloat16 g_xqh[Mm*Dd], g_xql[Mm*Dd];
__device__ __nv_bfloat16 g_xkh[Mm*Dd], g_xkl[Mm*Dd];
__device__ __nv_bfloat16 g_xvh[Mm*Dd], g_xvl[Mm*Dd];
__device__ __nv_bfloat16 g_wqh[Dd*Dd], g_wql[Dd*Dd];
__device__ __nv_bfloat16 g_wkh[Dd*Dd], g_wkl[Dd*Dd];
__device__ __nv_bfloat16 g_wvh[Dd*Dd], g_wvl[Dd*Dd];
__device__ __nv_bfloat16 g_woh[Dd*Dd], g_wol[Dd*Dd];
__device__ __nv_bfloat16 g_qh[Mm*Dd],  g_ql[Mm*Dd];
__device__ __nv_bfloat16 g_kh[Mm*Dd],  g_kl[Mm*Dd];
__device__ __nv_bfloat16 g_vh[Mm*Dd],  g_vl[Mm*Dd];
__device__ __nv_bfloat16 g_ch[Mm*Dd],  g_cl[Mm*Dd];

// ---------------------------------------------------------------------------
// Helpers
// ---------------------------------------------------------------------------
__device__ __forceinline__ uint32_t smem_u32(const void* p) {
    return (uint32_t)__cvta_generic_to_shared(p);
}
__device__ __forceinline__ void cp16(uint32_t dst, const void* src) {
    asm volatile("cp.async.cg.shared.global [%0], [%1], 16;\n" :: "r"(dst), "l"(src));
}
#define CP_COMMIT() asm volatile("cp.async.commit_group;\n" ::: "memory")
template<int N> __device__ __forceinline__ void cp_wait() {
    asm volatile("cp.async.wait_group %0;\n" :: "n"(N) : "memory");
}
__device__ __forceinline__ void ldmx4(uint32_t& r0, uint32_t& r1, uint32_t& r2, uint32_t& r3, uint32_t a) {
    asm volatile("ldmatrix.sync.aligned.m8n8.x4.shared.b16 {%0,%1,%2,%3}, [%4];\n"
        : "=r"(r0), "=r"(r1), "=r"(r2), "=r"(r3) : "r"(a));
}
__device__ __forceinline__ void ldmx4t(uint32_t& r0, uint32_t& r1, uint32_t& r2, uint32_t& r3, uint32_t a) {
    asm volatile("ldmatrix.sync.aligned.m8n8.x4.trans.shared.b16 {%0,%1,%2,%3}, [%4];\n"
        : "=r"(r0), "=r"(r1), "=r"(r2), "=r"(r3) : "r"(a));
}
__device__ __forceinline__ void mma16816(float* c, uint32_t a0, uint32_t a1, uint32_t a2, uint32_t a3,
                                         uint32_t b0, uint32_t b1) {
    asm volatile("mma.sync.aligned.m16n8k16.row.col.f32.bf16.bf16.f32 "
        "{%0,%1,%2,%3}, {%4,%5,%6,%7}, {%8,%9}, {%0,%1,%2,%3};\n"
        : "+f"(c[0]), "+f"(c[1]), "+f"(c[2]), "+f"(c[3])
        : "r"(a0), "r"(a1), "r"(a2), "r"(a3), "r"(b0), "r"(b1));
}
// pack two f32 -> bf16x2 (e0 in low half)
__device__ __forceinline__ uint32_t pack_bf16(float e0, float e1) {
    union { __nv_bfloat162 v; uint32_t u; } t;
    t.v = __floats2bfloat162_rn(e0, e1);
    return t.u;
}
__device__ __forceinline__ float lof(uint32_t p) { return __uint_as_float(p << 16); }
__device__ __forceinline__ float hif(uint32_t p) { return __uint_as_float(p & 0xFFFF0000u); }

// exp on the FMA pipe (no MUFU)
__device__ __forceinline__ float fast_exp(float x) {
    x = fmaxf(x, -80.0f);
    float y  = x * 1.4426950408889634f;
    float rr = y + 12582912.0f;
    float n  = rr - 12582912.0f;
    float f  = y - n;
    float p  = 1.3333558e-3f;
    p = fmaf(p, f, 9.6181291e-3f);
    p = fmaf(p, f, 5.5504109e-2f);
    p = fmaf(p, f, 2.4022651e-1f);
    p = fmaf(p, f, 6.9314718e-1f);
    p = fmaf(p, f, 1.0f);
    int e = __float_as_int(rr) - 0x4B400000;
    float s = __int_as_float((e + 127) << 23);
    return p * s;
}

// swizzled smem byte offset within a tile of 128B rows (8 chunks of 16B)
__device__ __forceinline__ uint32_t swz(int row, int chunk) {
    return (uint32_t)(row * 128 + ((chunk ^ (row & 7)) << 4));
}

// ---------------------------------------------------------------------------
// pre_split fused variants
// ---------------------------------------------------------------------------
__device__ __forceinline__ void split_one(const float4* __restrict__ X,
                                          uint32_t* __restrict__ Xh, uint32_t* __restrict__ Xl)
{
    int idx = blockIdx.x * 256 + threadIdx.x;
    float4 v = X[idx];
    uint32_t h0 = pack_bf16(v.x, v.y);
    uint32_t l0 = pack_bf16(v.x - lof(h0), v.y - hif(h0));
    uint32_t h1 = pack_bf16(v.z, v.w);
    uint32_t l1 = pack_bf16(v.z - lof(h1), v.w - hif(h1));
    Xh[idx*2]   = h0;  Xh[idx*2+1] = h1;
    Xl[idx*2]   = l0;  Xl[idx*2+1] = l1;
}

__global__ void pre_split3(const float4* __restrict__ A, const float4* __restrict__ B,
                           const float4* __restrict__ C,
                           uint32_t* __restrict__ Ah, uint32_t* __restrict__ Al,
                           uint32_t* __restrict__ Bh, uint32_t* __restrict__ Bl,
                           uint32_t* __restrict__ Ch, uint32_t* __restrict__ Cl)
{
    if (blockIdx.y == 0)      split_one(A, Ah, Al);
    else if (blockIdx.y == 1) split_one(B, Bh, Bl);
    else                      split_one(C, Ch, Cl);
}

__global__ void pre_split4(const float4* __restrict__ A, const float4* __restrict__ B,
                           const float4* __restrict__ C, const float4* __restrict__ D,
                           uint32_t* __restrict__ Ah, uint32_t* __restrict__ Al,
                           uint32_t* __restrict__ Bh, uint32_t* __restrict__ Bl,
                           uint32_t* __restrict__ Ch, uint32_t* __restrict__ Cl,
                           uint32_t* __restrict__ Dh, uint32_t* __restrict__ Dl)
{
    if (blockIdx.y == 0)      split_one(A, Ah, Al);
    else if (blockIdx.y == 1) split_one(B, Bh, Bl);
    else if (blockIdx.y == 2) split_one(C, Ch, Cl);
    else                      split_one(D, Dh, Dl);
}

// ---------------------------------------------------------------------------
// bf16x3 GEMM: C[4096,1024] = A @ W^T + bias
// BM=128 BN=128 BK=64, 3-stage cp.async, 16 warps (4m x 4n), warp 32x32.
// Passes reordered (hh all tiles, hl all tiles, lh all tiles) for ILP.
// ---------------------------------------------------------------------------
#define GST 65536                    // stage bytes: Ah|Al|Wh|Wl (16KB each)
#define GSMEM (3*GST)

__device__ __forceinline__ void gemm_load_stage(uint32_t base,
    const __nv_bfloat16* Ah, const __nv_bfloat16* Al,
    const __nv_bfloat16* Wh, const __nv_bfloat16* Wl,
    int m0, int n0, int k0, int tid)
{
#pragma unroll
    for (int i = 0; i < 2; i++) {
        int idx = tid + i * 512;          // 0..1023
        int r = idx >> 3, c = idx & 7;
        uint32_t so = swz(r, c);
        size_t ga = (size_t)(m0 + r) * Dd + k0 + c * 8;
        size_t gw = (size_t)(n0 + r) * Dd + k0 + c * 8;
        cp16(base + so,              Ah + ga);
        cp16(base + 16384 + so,      Al + ga);
        cp16(base + 32768 + so,      Wh + gw);
        cp16(base + 49152 + so,      Wl + gw);
    }
}

__global__ __launch_bounds__(512) void gemm_bf16x3(
    const __nv_bfloat16* __restrict__ Ah, const __nv_bfloat16* __restrict__ Al,
    const __nv_bfloat16* __restrict__ Wh, const __nv_bfloat16* __restrict__ Wl,
    const float* __restrict__ bias,
    float* __restrict__ Cf, uint32_t* __restrict__ Ch, uint32_t* __restrict__ Cl,
    int splitOut)
{
    extern __shared__ __align__(16) char sm[];
    const uint32_t smb = smem_u32(sm);
    const int tid = threadIdx.x, wid = tid >> 5, lane = tid & 31;
    const int m0 = blockIdx.y * 128, n0 = blockIdx.x * 128;
    const int wm = wid >> 2, wn = wid & 3;           // 4 x 4 warp grid, warp 32x32
    const int sub = lane >> 3, lr = lane & 7;

    float acc[2][4][4];
#pragma unroll
    for (int a = 0; a < 2; a++)
#pragma unroll
        for (int b = 0; b < 4; b++)
#pragma unroll
            for (int c = 0; c < 4; c++) acc[a][b][c] = 0.f;

    gemm_load_stage(smb,       Ah, Al, Wh, Wl, m0, n0, 0,  tid); CP_COMMIT();
    gemm_load_stage(smb + GST, Ah, Al, Wh, Wl, m0, n0, 64, tid); CP_COMMIT();

    for (int it = 0; it < 16; it++) {
        if (it + 2 < 16) {
            gemm_load_stage(smb + ((it+2)%3)*GST, Ah, Al, Wh, Wl, m0, n0, (it+2)*64, tid);
            CP_COMMIT();
            cp_wait<2>();
        } else {
            cp_wait<0>();
        }
        __syncthreads();
        uint32_t stg = smb + (it%3)*GST;
        uint32_t Abase = stg, Albase = stg + 16384, Wbase = stg + 32768, Wlbase = stg + 49152;

#pragma unroll
        for (int ks = 0; ks < 4; ks++) {
            uint32_t ah[2][4], al[2][4];
#pragma unroll
            for (int mt = 0; mt < 2; mt++) {
                int row = wm*32 + mt*16 + lr + (sub & 1)*8;
                int ch  = 2*ks + (sub >> 1);
                uint32_t so = swz(row, ch);
                ldmx4(ah[mt][0], ah[mt][1], ah[mt][2], ah[mt][3], Abase + so);
                ldmx4(al[mt][0], al[mt][1], al[mt][2], al[mt][3], Albase + so);
            }
            uint32_t bh[8], bl[8];   // [p pair: tiles 2p, 2p+1]
#pragma unroll
            for (int p = 0; p < 2; p++) {
                int row = wn*32 + p*16 + lr + (sub & 1)*8;
                int ch  = 2*ks + (sub >> 1);
                uint32_t so = swz(row, ch);
                ldmx4(bh[p*4+0], bh[p*4+1], bh[p*4+2], bh[p*4+3], Wbase + so);
                ldmx4(bl[p*4+0], bl[p*4+1], bl[p*4+2], bl[p*4+3], Wlbase + so);
            }
            // pass 1: ah x bh   (8 independent MMAs)
#pragma unroll
            for (int mt = 0; mt < 2; mt++)
#pragma unroll
                for (int p = 0; p < 2; p++) {
                    mma16816(acc[mt][2*p],   ah[mt][0],ah[mt][1],ah[mt][2],ah[mt][3], bh[p*4+0], bh[p*4+2]);
                    mma16816(acc[mt][2*p+1], ah[mt][0],ah[mt][1],ah[mt][2],ah[mt][3], bh[p*4+1], bh[p*4+3]);
                }
            // pass 2: ah x bl
#pragma unroll
            for (int mt = 0; mt < 2; mt++)
#pragma unroll
                for (int p = 0; p < 2; p++) {
                    mma16816(acc[mt][2*p],   ah[mt][0],ah[mt][1],ah[mt][2],ah[mt][3], bl[p*4+0], bl[p*4+2]);
                    mma16816(acc[mt][2*p+1], ah[mt][0],ah[mt][1],ah[mt][2],ah[mt][3], bl[p*4+1], bl[p*4+3]);
                }
            // pass 3: al x bh
#pragma unroll
            for (int mt = 0; mt < 2; mt++)
#pragma unroll
                for (int p = 0; p < 2; p++) {
                    mma16816(acc[mt][2*p],   al[mt][0],al[mt][1],al[mt][2],al[mt][3], bh[p*4+0], bh[p*4+2]);
                    mma16816(acc[mt][2*p+1], al[mt][0],al[mt][1],al[mt][2],al[mt][3], bh[p*4+1], bh[p*4+3]);
                }
        }
        __syncthreads();
    }

    // Epilogue
#pragma unroll
    for (int mt = 0; mt < 2; mt++) {
#pragma unroll
        for (int nt = 0; nt < 4; nt++) {
            int gr = m0 + wm*32 + mt*16 + (lane >> 2);
            int gc = n0 + wn*32 + nt*8 + (lane & 3)*2;
            float b0 = bias[gc], b1 = bias[gc+1];
            float v0 = acc[mt][nt][0] + b0, v1 = acc[mt][nt][1] + b1;
            float v2 = acc[mt][nt][2] + b0, v3 = acc[mt][nt][3] + b1;
            if (splitOut) {
                uint32_t h0 = pack_bf16(v0, v1);
                uint32_t l0 = pack_bf16(v0 - lof(h0), v1 - hif(h0));
                uint32_t h1 = pack_bf16(v2, v3);
                uint32_t l1 = pack_bf16(v2 - lof(h1), v3 - hif(h1));
                Ch[(size_t)gr*512 + (gc>>1)]       = h0;
                Cl[(size_t)gr*512 + (gc>>1)]       = l0;
                Ch[(size_t)(gr+8)*512 + (gc>>1)]   = h1;
                Cl[(size_t)(gr+8)*512 + (gc>>1)]   = l1;
            } else {
                *(float2*)(Cf + (size_t)gr*Dd + gc)     = make_float2(v0, v1);
                *(float2*)(Cf + (size_t)(gr+8)*Dd + gc) = make_float2(v2, v3);
            }
        }
    }
}

// ---------------------------------------------------------------------------
// Flash attention, bf16x3 mma. CTA = 128 q-rows of one (b,h). 8 warps,
// warp w owns rows [w*16, w*16+16). K/V double-buffered. P in registers.
// MMA pairs interleaved (distance-2 dependency).
// ---------------------------------------------------------------------------
#define AQH 0
#define AQL 16384
#define AKV 32768              // stage: KH | KL(+8192) | VH(+16384) | VL(+24576)
#define AKVST 32768
#define ASMEM (AKV + 2*AKVST)  // 98304

__device__ __forceinline__ void attn_load_kv(uint32_t base,
    const __nv_bfloat16* Kh, const __nv_bfloat16* Kl,
    const __nv_bfloat16* Vh, const __nv_bfloat16* Vl,
    size_t rowBase, int headOff, int k0, int tid)
{
#pragma unroll
    for (int i = 0; i < 2; i++) {
        int idx = tid + i * 256;          // 0..511 : 64 rows x 8 chunks
        int r = idx >> 3, c = idx & 7;
        uint32_t so = swz(r, c);
        size_t g = (rowBase + k0 + r) * Dd + headOff + c * 8;
        cp16(base + so,         Kh + g);
        cp16(base + 8192 + so,  Kl + g);
        cp16(base + 16384 + so, Vh + g);
        cp16(base + 24576 + so, Vl + g);
    }
}

__global__ __launch_bounds__(256, 2) void attn_kernel(
    const __nv_bfloat16* __restrict__ Qh, const __nv_bfloat16* __restrict__ Ql,
    const __nv_bfloat16* __restrict__ Kh, const __nv_bfloat16* __restrict__ Kl,
    const __nv_bfloat16* __restrict__ Vh, const __nv_bfloat16* __restrict__ Vl,
    uint32_t* __restrict__ Ch, uint32_t* __restrict__ Cl,
    const float* __restrict__ posr, const int* __restrict__ mask)
{
    extern __shared__ __align__(16) char sm[];
    const uint32_t smb = smem_u32(sm);
    const int tid = threadIdx.x, wid = tid >> 5, lane = tid & 31;
    const int sub = lane >> 3, lr = lane & 7;
    const int q0 = blockIdx.x * 128;
    const int h  = blockIdx.y;
    const int b  = blockIdx.z;
    const int headOff = h * 64;
    const size_t rowBase = (size_t)b * Ss;

    // load Q tile (128 x 64 hi+lo)
#pragma unroll
    for (int i = 0; i < 4; i++) {
        int idx = tid + i * 256;          // 0..1023
        int r = idx >> 3, c = idx & 7;
        uint32_t so = swz(r, c);
        size_t g = (rowBase + q0 + r) * Dd + headOff + c * 8;
        cp16(smb + AQH + so, Qh + g);
        cp16(smb + AQL + so, Ql + g);
    }
    attn_load_kv(smb + AKV, Kh, Kl, Vh, Vl, rowBase, headOff, 0, tid);
    CP_COMMIT();
    cp_wait<0>();
    __syncthreads();

    // preload Q fragments (warp-owned rows fixed)
    uint32_t qh[4][4], ql[4][4];
#pragma unroll
    for (int ks = 0; ks < 4; ks++) {
        int row = wid*16 + lr + (sub & 1)*8;
        int ch  = 2*ks + (sub >> 1);
        ldmx4(qh[ks][0], qh[ks][1], qh[ks][2], qh[ks][3], smb + AQH + swz(row, ch));
        ldmx4(ql[ks][0], ql[ks][1], ql[ks][2], ql[ks][3], smb + AQL + swz(row, ch));
    }

    float o[8][4];
#pragma unroll
    for (int i = 0; i < 8; i++)
#pragma unroll
        for (int j = 0; j < 4; j++) o[i][j] = 0.f;
    float mrow[2] = {-1e30f, -1e30f};
    float lrow[2] = {0.f, 0.f};

    const int r_lo = q0 + wid*16 + (lane >> 2);
    const int r_hi = r_lo + 8;
    const float* prLo = posr + ((size_t)b*Ss + r_lo)*Ss;
    const float* prHi = posr + ((size_t)b*Ss + r_hi)*Ss;
    const int*   mkB  = mask + b*Ss;

    for (int kt = 0; kt < 32; kt++) {
        uint32_t stg = smb + AKV + (kt & 1) * AKVST;
        if (kt + 1 < 32) {
            attn_load_kv(smb + AKV + ((kt+1) & 1) * AKVST, Kh, Kl, Vh, Vl,
                         rowBase, headOff, (kt+1)*64, tid);
            CP_COMMIT();
            cp_wait<1>();
        } else {
            cp_wait<0>();
        }
        __syncthreads();

        // ---- S = Q @ K^T (bf16x3, interleaved MMA pairs) ----
        float s[8][4];
#pragma unroll
        for (int i = 0; i < 8; i++)
#pragma unroll
            for (int j = 0; j < 4; j++) s[i][j] = 0.f;

#pragma unroll
        for (int ks = 0; ks < 4; ks++) {
#pragma unroll
            for (int p = 0; p < 4; p++) {    // pairs of n-tiles (2p, 2p+1)
                int row = p*16 + lr + (sub & 1)*8;
                int ch  = 2*ks + (sub >> 1);
                uint32_t so = swz(row, ch);
                uint32_t kh4[4], kl4[4];
                ldmx4(kh4[0], kh4[1], kh4[2], kh4[3], stg + so);
                ldmx4(kl4[0], kl4[1], kl4[2], kl4[3], stg + 8192 + so);
                mma16816(s[2*p],   qh[ks][0],qh[ks][1],qh[ks][2],qh[ks][3], kh4[0], kh4[2]);
                mma16816(s[2*p+1], qh[ks][0],qh[ks][1],qh[ks][2],qh[ks][3], kh4[1], kh4[3]);
                mma16816(s[2*p],   qh[ks][0],qh[ks][1],qh[ks][2],qh[ks][3], kl4[0], kl4[2]);
                mma16816(s[2*p+1], qh[ks][0],qh[ks][1],qh[ks][2],qh[ks][3], kl4[1], kl4[3]);
                mma16816(s[2*p],   ql[ks][0],ql[ks][1],ql[ks][2],ql[ks][3], kh4[0], kh4[2]);
                mma16816(s[2*p+1], ql[ks][0],ql[ks][1],ql[ks][2],ql[ks][3], kh4[1], kh4[3]);
            }
        }

        // ---- scale + posr + mask ----
        const int colB = kt*64 + (lane & 3)*2;
#pragma unroll
        for (int nt = 0; nt < 8; nt++) {
            int col = colB + nt*8;
            int2 mk = *(const int2*)(mkB + col);
            float2 p0 = *(const float2*)(prLo + col);
            float2 p1 = *(const float2*)(prHi + col);
            s[nt][0] = (mk.x != 0) ? fmaf(s[nt][0], 0.125f, p0.x) : -1e9f;
            s[nt][1] = (mk.y != 0) ? fmaf(s[nt][1], 0.125f, p0.y) : -1e9f;
            s[nt][2] = (mk.x != 0) ? fmaf(s[nt][2], 0.125f, p1.x) : -1e9f;
            s[nt][3] = (mk.y != 0) ? fmaf(s[nt][3], 0.125f, p1.y) : -1e9f;
        }

        // ---- online softmax ----
        float tm0 = -1e30f, tm1 = -1e30f;
#pragma unroll
        for (int nt = 0; nt < 8; nt++) {
            tm0 = fmaxf(tm0, fmaxf(s[nt][0], s[nt][1]));
            tm1 = fmaxf(tm1, fmaxf(s[nt][2], s[nt][3]));
        }
        tm0 = fmaxf(tm0, __shfl_xor_sync(0xffffffffu, tm0, 1));
        tm0 = fmaxf(tm0, __shfl_xor_sync(0xffffffffu, tm0, 2));
        tm1 = fmaxf(tm1, __shfl_xor_sync(0xffffffffu, tm1, 1));
        tm1 = fmaxf(tm1, __shfl_xor_sync(0xffffffffu, tm1, 2));

        float mn0 = fmaxf(mrow[0], tm0), mn1 = fmaxf(mrow[1], tm1);
        float f0 = fast_exp(mrow[0] - mn0), f1 = fast_exp(mrow[1] - mn1);
        mrow[0] = mn0; mrow[1] = mn1;

        float sum0 = 0.f, sum1 = 0.f;
#pragma unroll
        for (int nt = 0; nt < 8; nt++) {
            s[nt][0] = fast_exp(s[nt][0] - mn0);
            s[nt][1] = fast_exp(s[nt][1] - mn0);
            s[nt][2] = fast_exp(s[nt][2] - mn1);
            s[nt][3] = fast_exp(s[nt][3] - mn1);
            sum0 += s[nt][0] + s[nt][1];
            sum1 += s[nt][2] + s[nt][3];
        }
        sum0 += __shfl_xor_sync(0xffffffffu, sum0, 1);
        sum0 += __shfl_xor_sync(0xffffffffu, sum0, 2);
        sum1 += __shfl_xor_sync(0xffffffffu, sum1, 1);
        sum1 += __shfl_xor_sync(0xffffffffu, sum1, 2);
        lrow[0] = lrow[0] * f0 + sum0;
        lrow[1] = lrow[1] * f1 + sum1;

#pragma unroll
        for (int nt2 = 0; nt2 < 8; nt2++) {
            o[nt2][0] *= f0; o[nt2][1] *= f0;
            o[nt2][2] *= f1; o[nt2][3] *= f1;
        }

        // ---- pack P (hi/lo) into A-frags; acc += P @ V (interleaved) ----
#pragma unroll
        for (int ks = 0; ks < 4; ks++) {
            int t0 = 2*ks, t1 = 2*ks + 1;
            uint32_t ph0 = pack_bf16(s[t0][0], s[t0][1]);
            uint32_t ph1 = pack_bf16(s[t0][2], s[t0][3]);
            uint32_t ph2 = pack_bf16(s[t1][0], s[t1][1]);
            uint32_t ph3 = pack_bf16(s[t1][2], s[t1][3]);
            uint32_t pl0 = pack_bf16(s[t0][0] - lof(ph0), s[t0][1] - hif(ph0));
            uint32_t pl1 = pack_bf16(s[t0][2] - lof(ph1), s[t0][3] - hif(ph1));
            uint32_t pl2 = pack_bf16(s[t1][0] - lof(ph2), s[t1][1] - hif(ph2));
            uint32_t pl3 = pack_bf16(s[t1][2] - lof(ph3), s[t1][3] - hif(ph3));
            int row = ks*16 + (lane & 15);
#pragma unroll
            for (int np = 0; np < 4; np++) {   // pairs of d-tiles (2np, 2np+1)
                uint32_t so = swz(row, np*2 + (lane >> 4));
                uint32_t h0,h1,h2,h3, l0,l1,l2,l3;
                ldmx4t(h0,h1,h2,h3, stg + 16384 + so);
                ldmx4t(l0,l1,l2,l3, stg + 24576 + so);
                mma16816(o[2*np],   ph0,ph1,ph2,ph3, h0,h1);
                mma16816(o[2*np+1], ph0,ph1,ph2,ph3, h2,h3);
                mma16816(o[2*np],   ph0,ph1,ph2,ph3, l0,l1);
                mma16816(o[2*np+1], ph0,ph1,ph2,ph3, l2,l3);
                mma16816(o[2*np],   pl0,pl1,pl2,pl3, h0,h1);
                mma16816(o[2*np+1], pl0,pl1,pl2,pl3, h2,h3);
            }
        }
        __syncthreads();
    }

    // ---- epilogue: normalize, split hi/lo, write ctx ----
    float inv0 = 1.f / lrow[0], inv1 = 1.f / lrow[1];
    const size_t grLo = rowBase + (size_t)r_lo;
    const size_t grHi = rowBase + (size_t)r_hi;
#pragma unroll
    for (int nt2 = 0; nt2 < 8; nt2++) {
        int gc = headOff + nt2*8 + (lane & 3)*2;
        float v0 = o[nt2][0] * inv0, v1 = o[nt2][1] * inv0;
        float v2 = o[nt2][2] * inv1, v3 = o[nt2][3] * inv1;
        uint32_t h0 = pack_bf16(v0, v1);
        uint32_t l0 = pack_bf16(v0 - lof(h0), v1 - hif(h0));
        uint32_t h1 = pack_bf16(v2, v3);
        uint32_t l1 = pack_bf16(v2 - lof(h1), v3 - hif(h1));
        Ch[grLo*512 + (gc>>1)] = h0;
        Cl[grLo*512 + (gc>>1)] = l0;
        Ch[grHi*512 + (gc>>1)] = h1;
        Cl[grHi*512 + (gc>>1)] = l1;
    }
}

// ---------------------------------------------------------------------------
extern "C" void kernel_launch(void* const* d_in, const int* in_sizes, int n_in,
                              void* d_out, int out_size)
{
    const float* query = (const float*)d_in[0];
    const float* key   = (const float*)d_in[1];
    const float* value = (const float*)d_in[2];
    const int*   mask  = (const int*)  d_in[3];
    const float* posr  = (const float*)d_in[4];
    const float* Wq    = (const float*)d_in[5];
    const float* bq    = (const float*)d_in[6];
    const float* Wk    = (const float*)d_in[7];
    const float* bk    = (const float*)d_in[8];
    const float* Wv    = (const float*)d_in[9];
    const float* bv    = (const float*)d_in[10];
    const float* Wo    = (const float*)d_in[11];
    const float* bo    = (const float*)d_in[12];
    float* out = (float*)d_out;

    __nv_bfloat16 *xqh,*xql,*xkh,*xkl,*xvh,*xvl;
    __nv_bfloat16 *wqh,*wql,*wkh,*wkl,*wvh,*wvl,*woh,*wol;
    __nv_bfloat16 *qh,*ql,*kh,*kl,*vh,*vl,*ch,*cl;
    cudaGetSymbolAddress((void**)&xqh, g_xqh); cudaGetSymbolAddress((void**)&xql, g_xql);
    cudaGetSymbolAddress((void**)&xkh, g_xkh); cudaGetSymbolAddress((void**)&xkl, g_xkl);
    cudaGetSymbolAddress((void**)&xvh, g_xvh); cudaGetSymbolAddress((void**)&xvl, g_xvl);
    cudaGetSymbolAddress((void**)&wqh, g_wqh); cudaGetSymbolAddress((void**)&wql, g_wql);
    cudaGetSymbolAddress((void**)&wkh, g_wkh); cudaGetSymbolAddress((void**)&wkl, g_wkl);
    cudaGetSymbolAddress((void**)&wvh, g_wvh); cudaGetSymbolAddress((void**)&wvl, g_wvl);
    cudaGetSymbolAddress((void**)&woh, g_woh); cudaGetSymbolAddress((void**)&wol, g_wol);
    cudaGetSymbolAddress((void**)&qh, g_qh);   cudaGetSymbolAddress((void**)&ql, g_ql);
    cudaGetSymbolAddress((void**)&kh, g_kh);   cudaGetSymbolAddress((void**)&kl, g_kl);
    cudaGetSymbolAddress((void**)&vh, g_vh);   cudaGetSymbolAddress((void**)&vl, g_vl);
    cudaGetSymbolAddress((void**)&ch, g_ch);   cudaGetSymbolAddress((void**)&cl, g_cl);

    pre_split3<<<dim3(Mm, 3), 256>>>((const float4*)query, (const float4*)key, (const float4*)value,
        (uint32_t*)xqh, (uint32_t*)xql, (uint32_t*)xkh, (uint32_t*)xkl, (uint32_t*)xvh, (uint32_t*)xvl);
    pre_split4<<<dim3(Dd, 4), 256>>>((const float4*)Wq, (const float4*)Wk, (const float4*)Wv, (const float4*)Wo,
        (uint32_t*)wqh, (uint32_t*)wql, (uint32_t*)wkh, (uint32_t*)wkl,
        (uint32_t*)wvh, (uint32_t*)wvl, (uint32_t*)woh, (uint32_t*)wol);

    cudaFuncSetAttribute(gemm_bf16x3, cudaFuncAttributeMaxDynamicSharedMemorySize, GSMEM);
    cudaFuncSetAttribute(attn_kernel, cudaFuncAttributeMaxDynamicSharedMemorySize, ASMEM);

    dim3 gGrid(Dd/128, Mm/128);   // (8, 32)
    gemm_bf16x3<<<gGrid, 512, GSMEM>>>(xqh, xql, wqh, wql, bq, nullptr, (uint32_t*)qh, (uint32_t*)ql, 1);
    gemm_bf16x3<<<gGrid, 512, GSMEM>>>(xkh, xkl, wkh, wkl, bk, nullptr, (uint32_t*)kh, (uint32_t*)kl, 1);
    gemm_bf16x3<<<gGrid, 512, GSMEM>>>(xvh, xvl, wvh, wvl, bv, nullptr, (uint32_t*)vh, (uint32_t*)vl, 1);

    // launch #6 (ncu -s 5 -c 1 captures this one)
    attn_kernel<<<dim3(Ss/128, Hh, Bb), 256, ASMEM>>>(qh, ql, kh, kl, vh, vl,
        (uint32_t*)ch, (uint32_t*)cl, posr, mask);

    gemm_bf16x3<<<gGrid, 512, GSMEM>>>(ch, cl, woh, wol, bo, out, nullptr, nullptr, 0);
}

// round 7
// speedup vs baseline: 3.5651x; 1.3531x over previous
#include <cuda_runtime.h>
#include <cuda_fp16.h>
#include <math.h>
#include <stdint.h>

#define Bb 2
#define Ss 2048
#define Dd 1024
#define Hh 16
#define Mm 4096

// ---------------------------------------------------------------------------
// Scratch (device globals), fp16
// ---------------------------------------------------------------------------
__device__ __half g_xq[Mm*Dd], g_xk[Mm*Dd], g_xv[Mm*Dd];      // inputs, plain
__device__ __half g_wqh[Dd*Dd], g_wql[Dd*Dd];
__device__ __half g_wkh[Dd*Dd], g_wkl[Dd*Dd];
__device__ __half g_wvh[Dd*Dd], g_wvl[Dd*Dd];
__device__ __half g_woh[Dd*Dd], g_wol[Dd*Dd];
__device__ __half g_q[Mm*Dd];                                  // q plain
__device__ __half g_kh[Mm*Dd], g_kl[Mm*Dd];                    // k split
__device__ __half g_vh[Mm*Dd], g_vl[Mm*Dd];                    // v split
__device__ __half g_c[Mm*Dd];                                  // ctx plain

// ---------------------------------------------------------------------------
// Helpers
// ---------------------------------------------------------------------------
__device__ __forceinline__ uint32_t smem_u32(const void* p) {
    return (uint32_t)__cvta_generic_to_shared(p);
}
__device__ __forceinline__ void cp16(uint32_t dst, const void* src) {
    asm volatile("cp.async.cg.shared.global [%0], [%1], 16;\n" :: "r"(dst), "l"(src));
}
#define CP_COMMIT() asm volatile("cp.async.commit_group;\n" ::: "memory")
template<int N> __device__ __forceinline__ void cp_wait() {
    asm volatile("cp.async.wait_group %0;\n" :: "n"(N) : "memory");
}
__device__ __forceinline__ void ldmx4(uint32_t& r0, uint32_t& r1, uint32_t& r2, uint32_t& r3, uint32_t a) {
    asm volatile("ldmatrix.sync.aligned.m8n8.x4.shared.b16 {%0,%1,%2,%3}, [%4];\n"
        : "=r"(r0), "=r"(r1), "=r"(r2), "=r"(r3) : "r"(a));
}
__device__ __forceinline__ void ldmx4t(uint32_t& r0, uint32_t& r1, uint32_t& r2, uint32_t& r3, uint32_t a) {
    asm volatile("ldmatrix.sync.aligned.m8n8.x4.trans.shared.b16 {%0,%1,%2,%3}, [%4];\n"
        : "=r"(r0), "=r"(r1), "=r"(r2), "=r"(r3) : "r"(a));
}
__device__ __forceinline__ void mma16816(float* c, uint32_t a0, uint32_t a1, uint32_t a2, uint32_t a3,
                                         uint32_t b0, uint32_t b1) {
    asm volatile("mma.sync.aligned.m16n8k16.row.col.f32.f16.f16.f32 "
        "{%0,%1,%2,%3}, {%4,%5,%6,%7}, {%8,%9}, {%0,%1,%2,%3};\n"
        : "+f"(c[0]), "+f"(c[1]), "+f"(c[2]), "+f"(c[3])
        : "r"(a0), "r"(a1), "r"(a2), "r"(a3), "r"(b0), "r"(b1));
}
// pack two f32 -> fp16x2 (e0 in low half)
__device__ __forceinline__ uint32_t pack_h(float e0, float e1) {
    union { __half2 v; uint32_t u; } t;
    t.v = __floats2half2_rn(e0, e1);
    return t.u;
}
__device__ __forceinline__ float lo_h(uint32_t p) {
    union { uint32_t u; __half2 v; } t; t.u = p; return __low2float(t.v);
}
__device__ __forceinline__ float hi_h(uint32_t p) {
    union { uint32_t u; __half2 v; } t; t.u = p; return __high2float(t.v);
}

// exp on the FMA pipe (no MUFU)
__device__ __forceinline__ float fast_exp(float x) {
    x = fmaxf(x, -80.0f);
    float y  = x * 1.4426950408889634f;
    float rr = y + 12582912.0f;
    float n  = rr - 12582912.0f;
    float f  = y - n;
    float p  = 1.3333558e-3f;
    p = fmaf(p, f, 9.6181291e-3f);
    p = fmaf(p, f, 5.5504109e-2f);
    p = fmaf(p, f, 2.4022651e-1f);
    p = fmaf(p, f, 6.9314718e-1f);
    p = fmaf(p, f, 1.0f);
    int e = __float_as_int(rr) - 0x4B400000;
    float s = __int_as_float((e + 127) << 23);
    return p * s;
}

// swizzled smem byte offset within a tile of 128B rows (8 chunks of 16B)
__device__ __forceinline__ uint32_t swz(int row, int chunk) {
    return (uint32_t)(row * 128 + ((chunk ^ (row & 7)) << 4));
}

// ---------------------------------------------------------------------------
// Preprocess: plain fp16 convert for activations; hi/lo split for weights.
// ---------------------------------------------------------------------------
__global__ void pre_cvt3(const float4* __restrict__ A, const float4* __restrict__ B,
                         const float4* __restrict__ C,
                         uint32_t* __restrict__ Ao, uint32_t* __restrict__ Bo,
                         uint32_t* __restrict__ Co)
{
    int idx = blockIdx.x * 256 + threadIdx.x;
    const float4* X = (blockIdx.y == 0) ? A : (blockIdx.y == 1) ? B : C;
    uint32_t*     Y = (blockIdx.y == 0) ? Ao : (blockIdx.y == 1) ? Bo : Co;
    float4 v = X[idx];
    Y[idx*2]   = pack_h(v.x, v.y);
    Y[idx*2+1] = pack_h(v.z, v.w);
}

__device__ __forceinline__ void split_one(const float4* __restrict__ X,
                                          uint32_t* __restrict__ Xh, uint32_t* __restrict__ Xl)
{
    int idx = blockIdx.x * 256 + threadIdx.x;
    float4 v = X[idx];
    uint32_t h0 = pack_h(v.x, v.y);
    uint32_t l0 = pack_h(v.x - lo_h(h0), v.y - hi_h(h0));
    uint32_t h1 = pack_h(v.z, v.w);
    uint32_t l1 = pack_h(v.z - lo_h(h1), v.w - hi_h(h1));
    Xh[idx*2]   = h0;  Xh[idx*2+1] = h1;
    Xl[idx*2]   = l0;  Xl[idx*2+1] = l1;
}

__global__ void pre_split4(const float4* __restrict__ A, const float4* __restrict__ B,
                           const float4* __restrict__ C, const float4* __restrict__ D,
                           uint32_t* __restrict__ Ah, uint32_t* __restrict__ Al,
                           uint32_t* __restrict__ Bh, uint32_t* __restrict__ Bl,
                           uint32_t* __restrict__ Ch, uint32_t* __restrict__ Cl,
                           uint32_t* __restrict__ Dh, uint32_t* __restrict__ Dl)
{
    if (blockIdx.y == 0)      split_one(A, Ah, Al);
    else if (blockIdx.y == 1) split_one(B, Bh, Bl);
    else if (blockIdx.y == 2) split_one(C, Ch, Cl);
    else                      split_one(D, Dh, Dl);
}

// ---------------------------------------------------------------------------
// fp16 2-pass GEMM: C[4096,1024] = A @ (Wh+Wl)^T + bias
// BM=128 BN=128 BK=64, 3-stage cp.async, 16 warps (4m x 4n), warp 32x32.
// outMode: 0 = fp32, 1 = plain fp16, 2 = split fp16 (hi/lo)
// ---------------------------------------------------------------------------
#define GST 49152                    // stage bytes: A | Wh | Wl (16KB each)
#define GSMEM (3*GST)

__device__ __forceinline__ void gemm_load_stage(uint32_t base,
    const __half* A, const __half* Wh, const __half* Wl,
    int m0, int n0, int k0, int tid)
{
#pragma unroll
    for (int i = 0; i < 2; i++) {
        int idx = tid + i * 512;          // 0..1023
        int r = idx >> 3, c = idx & 7;
        uint32_t so = swz(r, c);
        cp16(base + so,         A  + (size_t)(m0 + r) * Dd + k0 + c * 8);
        cp16(base + 16384 + so, Wh + (size_t)(n0 + r) * Dd + k0 + c * 8);
        cp16(base + 32768 + so, Wl + (size_t)(n0 + r) * Dd + k0 + c * 8);
    }
}

__global__ __launch_bounds__(512) void gemm_f16x2(
    const __half* __restrict__ A,
    const __half* __restrict__ Wh, const __half* __restrict__ Wl,
    const float* __restrict__ bias,
    float* __restrict__ Cf, uint32_t* __restrict__ Co, uint32_t* __restrict__ Col,
    int outMode)
{
    extern __shared__ __align__(16) char sm[];
    const uint32_t smb = smem_u32(sm);
    const int tid = threadIdx.x, wid = tid >> 5, lane = tid & 31;
    const int m0 = blockIdx.y * 128, n0 = blockIdx.x * 128;
    const int wm = wid >> 2, wn = wid & 3;           // 4 x 4 warp grid, warp 32x32
    const int sub = lane >> 3, lr = lane & 7;

    float acc[2][4][4];
#pragma unroll
    for (int a = 0; a < 2; a++)
#pragma unroll
        for (int b = 0; b < 4; b++)
#pragma unroll
            for (int c = 0; c < 4; c++) acc[a][b][c] = 0.f;

    gemm_load_stage(smb,       A, Wh, Wl, m0, n0, 0,  tid); CP_COMMIT();
    gemm_load_stage(smb + GST, A, Wh, Wl, m0, n0, 64, tid); CP_COMMIT();

    for (int it = 0; it < 16; it++) {
        if (it + 2 < 16) {
            gemm_load_stage(smb + ((it+2)%3)*GST, A, Wh, Wl, m0, n0, (it+2)*64, tid);
            CP_COMMIT();
            cp_wait<2>();
        } else {
            cp_wait<0>();
        }
        __syncthreads();
        uint32_t stg = smb + (it%3)*GST;

#pragma unroll
        for (int ks = 0; ks < 4; ks++) {
            uint32_t ah[2][4];
#pragma unroll
            for (int mt = 0; mt < 2; mt++) {
                int row = wm*32 + mt*16 + lr + (sub & 1)*8;
                int ch  = 2*ks + (sub >> 1);
                ldmx4(ah[mt][0], ah[mt][1], ah[mt][2], ah[mt][3], stg + swz(row, ch));
            }
            uint32_t bh[8], bl[8];   // [p pair: tiles 2p, 2p+1]
#pragma unroll
            for (int p = 0; p < 2; p++) {
                int row = wn*32 + p*16 + lr + (sub & 1)*8;
                int ch  = 2*ks + (sub >> 1);
                uint32_t so = swz(row, ch);
                ldmx4(bh[p*4+0], bh[p*4+1], bh[p*4+2], bh[p*4+3], stg + 16384 + so);
                ldmx4(bl[p*4+0], bl[p*4+1], bl[p*4+2], bl[p*4+3], stg + 32768 + so);
            }
            // pass 1: a x Wh  (8 independent MMAs)
#pragma unroll
            for (int mt = 0; mt < 2; mt++)
#pragma unroll
                for (int p = 0; p < 2; p++) {
                    mma16816(acc[mt][2*p],   ah[mt][0],ah[mt][1],ah[mt][2],ah[mt][3], bh[p*4+0], bh[p*4+2]);
                    mma16816(acc[mt][2*p+1], ah[mt][0],ah[mt][1],ah[mt][2],ah[mt][3], bh[p*4+1], bh[p*4+3]);
                }
            // pass 2: a x Wl
#pragma unroll
            for (int mt = 0; mt < 2; mt++)
#pragma unroll
                for (int p = 0; p < 2; p++) {
                    mma16816(acc[mt][2*p],   ah[mt][0],ah[mt][1],ah[mt][2],ah[mt][3], bl[p*4+0], bl[p*4+2]);
                    mma16816(acc[mt][2*p+1], ah[mt][0],ah[mt][1],ah[mt][2],ah[mt][3], bl[p*4+1], bl[p*4+3]);
                }
        }
        __syncthreads();
    }

    // Epilogue
#pragma unroll
    for (int mt = 0; mt < 2; mt++) {
#pragma unroll
        for (int nt = 0; nt < 4; nt++) {
            int gr = m0 + wm*32 + mt*16 + (lane >> 2);
            int gc = n0 + wn*32 + nt*8 + (lane & 3)*2;
            float b0 = bias[gc], b1 = bias[gc+1];
            float v0 = acc[mt][nt][0] + b0, v1 = acc[mt][nt][1] + b1;
            float v2 = acc[mt][nt][2] + b0, v3 = acc[mt][nt][3] + b1;
            if (outMode == 0) {
                *(float2*)(Cf + (size_t)gr*Dd + gc)     = make_float2(v0, v1);
                *(float2*)(Cf + (size_t)(gr+8)*Dd + gc) = make_float2(v2, v3);
            } else if (outMode == 1) {
                Co[(size_t)gr*512 + (gc>>1)]     = pack_h(v0, v1);
                Co[(size_t)(gr+8)*512 + (gc>>1)] = pack_h(v2, v3);
            } else {
                uint32_t h0 = pack_h(v0, v1);
                uint32_t l0 = pack_h(v0 - lo_h(h0), v1 - hi_h(h0));
                uint32_t h1 = pack_h(v2, v3);
                uint32_t l1 = pack_h(v2 - lo_h(h1), v3 - hi_h(h1));
                Co[(size_t)gr*512 + (gc>>1)]      = h0;
                Col[(size_t)gr*512 + (gc>>1)]     = l0;
                Co[(size_t)(gr+8)*512 + (gc>>1)]  = h1;
                Col[(size_t)(gr+8)*512 + (gc>>1)] = l1;
            }
        }
    }
}

// ---------------------------------------------------------------------------
// Flash attention, fp16 2-pass. CTA = 128 q-rows of one (b,h). 8 warps.
// Q plain fp16; K,V split hi/lo. P plain fp16. K/V double-buffered.
// ---------------------------------------------------------------------------
#define AQ 0
#define AKV 16384              // stage: KH | KL(+8192) | VH(+16384) | VL(+24576)
#define AKVST 32768
#define ASMEM (AKV + 2*AKVST)  // 81920

__device__ __forceinline__ void attn_load_kv(uint32_t base,
    const __half* Kh, const __half* Kl, const __half* Vh, const __half* Vl,
    size_t rowBase, int headOff, int k0, int tid)
{
#pragma unroll
    for (int i = 0; i < 2; i++) {
        int idx = tid + i * 256;          // 0..511 : 64 rows x 8 chunks
        int r = idx >> 3, c = idx & 7;
        uint32_t so = swz(r, c);
        size_t g = (rowBase + k0 + r) * Dd + headOff + c * 8;
        cp16(base + so,         Kh + g);
        cp16(base + 8192 + so,  Kl + g);
        cp16(base + 16384 + so, Vh + g);
        cp16(base + 24576 + so, Vl + g);
    }
}

__global__ __launch_bounds__(256, 2) void attn_kernel(
    const __half* __restrict__ Q,
    const __half* __restrict__ Kh, const __half* __restrict__ Kl,
    const __half* __restrict__ Vh, const __half* __restrict__ Vl,
    uint32_t* __restrict__ Co,
    const float* __restrict__ posr, const int* __restrict__ mask)
{
    extern __shared__ __align__(16) char sm[];
    const uint32_t smb = smem_u32(sm);
    const int tid = threadIdx.x, wid = tid >> 5, lane = tid & 31;
    const int sub = lane >> 3, lr = lane & 7;
    const int q0 = blockIdx.x * 128;
    const int h  = blockIdx.y;
    const int b  = blockIdx.z;
    const int headOff = h * 64;
    const size_t rowBase = (size_t)b * Ss;

    // load Q tile (128 x 64 fp16)
#pragma unroll
    for (int i = 0; i < 2; i++) {
        int idx = tid + i * 256;          // need 0..1023 -> 4 iters of 256; use 2x512? 256 threads
        int r = (idx << 1) >> 3;          // unused placeholder
    }
#pragma unroll
    for (int i = 0; i < 4; i++) {
        int idx = tid + i * 256;          // 0..1023
        int r = idx >> 3, c = idx & 7;
        cp16(smb + AQ + swz(r, c), Q + (rowBase + q0 + r) * Dd + headOff + c * 8);
    }
    attn_load_kv(smb + AKV, Kh, Kl, Vh, Vl, rowBase, headOff, 0, tid);
    CP_COMMIT();
    cp_wait<0>();
    __syncthreads();

    // preload Q fragments (warp-owned rows fixed)
    uint32_t qf[4][4];
#pragma unroll
    for (int ks = 0; ks < 4; ks++) {
        int row = wid*16 + lr + (sub & 1)*8;
        int ch  = 2*ks + (sub >> 1);
        ldmx4(qf[ks][0], qf[ks][1], qf[ks][2], qf[ks][3], smb + AQ + swz(row, ch));
    }

    float o[8][4];
#pragma unroll
    for (int i = 0; i < 8; i++)
#pragma unroll
        for (int j = 0; j < 4; j++) o[i][j] = 0.f;
    float mrow[2] = {-1e30f, -1e30f};
    float lrow[2] = {0.f, 0.f};

    const int r_lo = q0 + wid*16 + (lane >> 2);
    const int r_hi = r_lo + 8;
    const float* prLo = posr + ((size_t)b*Ss + r_lo)*Ss;
    const float* prHi = posr + ((size_t)b*Ss + r_hi)*Ss;
    const int*   mkB  = mask + b*Ss;

    for (int kt = 0; kt < 32; kt++) {
        uint32_t stg = smb + AKV + (kt & 1) * AKVST;
        if (kt + 1 < 32) {
            attn_load_kv(smb + AKV + ((kt+1) & 1) * AKVST, Kh, Kl, Vh, Vl,
                         rowBase, headOff, (kt+1)*64, tid);
            CP_COMMIT();
            cp_wait<1>();
        } else {
            cp_wait<0>();
        }
        __syncthreads();

        // ---- S = Q @ K^T (fp16 2-pass, interleaved MMA pairs) ----
        float s[8][4];
#pragma unroll
        for (int i = 0; i < 8; i++)
#pragma unroll
            for (int j = 0; j < 4; j++) s[i][j] = 0.f;

#pragma unroll
        for (int ks = 0; ks < 4; ks++) {
#pragma unroll
            for (int p = 0; p < 4; p++) {    // pairs of n-tiles (2p, 2p+1)
                int row = p*16 + lr + (sub & 1)*8;
                int ch  = 2*ks + (sub >> 1);
                uint32_t so = swz(row, ch);
                uint32_t kh4[4], kl4[4];
                ldmx4(kh4[0], kh4[1], kh4[2], kh4[3], stg + so);
                ldmx4(kl4[0], kl4[1], kl4[2], kl4[3], stg + 8192 + so);
                mma16816(s[2*p],   qf[ks][0],qf[ks][1],qf[ks][2],qf[ks][3], kh4[0], kh4[2]);
                mma16816(s[2*p+1], qf[ks][0],qf[ks][1],qf[ks][2],qf[ks][3], kh4[1], kh4[3]);
                mma16816(s[2*p],   qf[ks][0],qf[ks][1],qf[ks][2],qf[ks][3], kl4[0], kl4[2]);
                mma16816(s[2*p+1], qf[ks][0],qf[ks][1],qf[ks][2],qf[ks][3], kl4[1], kl4[3]);
            }
        }

        // ---- scale + posr + mask ----
        const int colB = kt*64 + (lane & 3)*2;
#pragma unroll
        for (int nt = 0; nt < 8; nt++) {
            int col = colB + nt*8;
            int2 mk = *(const int2*)(mkB + col);
            float2 p0 = *(const float2*)(prLo + col);
            float2 p1 = *(const float2*)(prHi + col);
            s[nt][0] = (mk.x != 0) ? fmaf(s[nt][0], 0.125f, p0.x) : -1e9f;
            s[nt][1] = (mk.y != 0) ? fmaf(s[nt][1], 0.125f, p0.y) : -1e9f;
            s[nt][2] = (mk.x != 0) ? fmaf(s[nt][2], 0.125f, p1.x) : -1e9f;
            s[nt][3] = (mk.y != 0) ? fmaf(s[nt][3], 0.125f, p1.y) : -1e9f;
        }

        // ---- online softmax ----
        float tm0 = -1e30f, tm1 = -1e30f;
#pragma unroll
        for (int nt = 0; nt < 8; nt++) {
            tm0 = fmaxf(tm0, fmaxf(s[nt][0], s[nt][1]));
            tm1 = fmaxf(tm1, fmaxf(s[nt][2], s[nt][3]));
        }
        tm0 = fmaxf(tm0, __shfl_xor_sync(0xffffffffu, tm0, 1));
        tm0 = fmaxf(tm0, __shfl_xor_sync(0xffffffffu, tm0, 2));
        tm1 = fmaxf(tm1, __shfl_xor_sync(0xffffffffu, tm1, 1));
        tm1 = fmaxf(tm1, __shfl_xor_sync(0xffffffffu, tm1, 2));

        float mn0 = fmaxf(mrow[0], tm0), mn1 = fmaxf(mrow[1], tm1);
        float f0 = fast_exp(mrow[0] - mn0), f1 = fast_exp(mrow[1] - mn1);
        mrow[0] = mn0; mrow[1] = mn1;

        float sum0 = 0.f, sum1 = 0.f;
#pragma unroll
        for (int nt = 0; nt < 8; nt++) {
            s[nt][0] = fast_exp(s[nt][0] - mn0);
            s[nt][1] = fast_exp(s[nt][1] - mn0);
            s[nt][2] = fast_exp(s[nt][2] - mn1);
            s[nt][3] = fast_exp(s[nt][3] - mn1);
            sum0 += s[nt][0] + s[nt][1];
            sum1 += s[nt][2] + s[nt][3];
        }
        sum0 += __shfl_xor_sync(0xffffffffu, sum0, 1);
        sum0 += __shfl_xor_sync(0xffffffffu, sum0, 2);
        sum1 += __shfl_xor_sync(0xffffffffu, sum1, 1);
        sum1 += __shfl_xor_sync(0xffffffffu, sum1, 2);
        lrow[0] = lrow[0] * f0 + sum0;
        lrow[1] = lrow[1] * f1 + sum1;

#pragma unroll
        for (int nt2 = 0; nt2 < 8; nt2++) {
            o[nt2][0] *= f0; o[nt2][1] *= f0;
            o[nt2][2] *= f1; o[nt2][3] *= f1;
        }

        // ---- pack P (plain fp16) into A-frags; acc += P @ (Vh+Vl) ----
#pragma unroll
        for (int ks = 0; ks < 4; ks++) {
            int t0 = 2*ks, t1 = 2*ks + 1;
            uint32_t ph0 = pack_h(s[t0][0], s[t0][1]);
            uint32_t ph1 = pack_h(s[t0][2], s[t0][3]);
            uint32_t ph2 = pack_h(s[t1][0], s[t1][1]);
            uint32_t ph3 = pack_h(s[t1][2], s[t1][3]);
            int row = ks*16 + (lane & 15);
#pragma unroll
            for (int np = 0; np < 4; np++) {   // pairs of d-tiles (2np, 2np+1)
                uint32_t so = swz(row, np*2 + (lane >> 4));
                uint32_t h0,h1,h2,h3, l0,l1,l2,l3;
                ldmx4t(h0,h1,h2,h3, stg + 16384 + so);
                ldmx4t(l0,l1,l2,l3, stg + 24576 + so);
                mma16816(o[2*np],   ph0,ph1,ph2,ph3, h0,h1);
                mma16816(o[2*np+1], ph0,ph1,ph2,ph3, h2,h3);
                mma16816(o[2*np],   ph0,ph1,ph2,ph3, l0,l1);
                mma16816(o[2*np+1], ph0,ph1,ph2,ph3, l2,l3);
            }
        }
        __syncthreads();
    }

    // ---- epilogue: normalize, write ctx (plain fp16) ----
    float inv0 = 1.f / lrow[0], inv1 = 1.f / lrow[1];
    const size_t grLo = rowBase + (size_t)r_lo;
    const size_t grHi = rowBase + (size_t)r_hi;
#pragma unroll
    for (int nt2 = 0; nt2 < 8; nt2++) {
        int gc = headOff + nt2*8 + (lane & 3)*2;
        Co[grLo*512 + (gc>>1)] = pack_h(o[nt2][0] * inv0, o[nt2][1] * inv0);
        Co[grHi*512 + (gc>>1)] = pack_h(o[nt2][2] * inv1, o[nt2][3] * inv1);
    }
}

// ---------------------------------------------------------------------------
extern "C" void kernel_launch(void* const* d_in, const int* in_sizes, int n_in,
                              void* d_out, int out_size)
{
    const float* query = (const float*)d_in[0];
    const float* key   = (const float*)d_in[1];
    const float* value = (const float*)d_in[2];
    const int*   mask  = (const int*)  d_in[3];
    const float* posr  = (const float*)d_in[4];
    const float* Wq    = (const float*)d_in[5];
    const float* bq    = (const float*)d_in[6];
    const float* Wk    = (const float*)d_in[7];
    const float* bk    = (const float*)d_in[8];
    const float* Wv    = (const float*)d_in[9];
    const float* bv    = (const float*)d_in[10];
    const float* Wo    = (const float*)d_in[11];
    const float* bo    = (const float*)d_in[12];
    float* out = (float*)d_out;

    __half *xq,*xk,*xv, *q16, *kh,*kl, *vh,*vl, *c16;
    __half *wqh,*wql,*wkh,*wkl,*wvh,*wvl,*woh,*wol;
    cudaGetSymbolAddress((void**)&xq, g_xq);   cudaGetSymbolAddress((void**)&xk, g_xk);
    cudaGetSymbolAddress((void**)&xv, g_xv);
    cudaGetSymbolAddress((void**)&wqh, g_wqh); cudaGetSymbolAddress((void**)&wql, g_wql);
    cudaGetSymbolAddress((void**)&wkh, g_wkh); cudaGetSymbolAddress((void**)&wkl, g_wkl);
    cudaGetSymbolAddress((void**)&wvh, g_wvh); cudaGetSymbolAddress((void**)&wvl, g_wvl);
    cudaGetSymbolAddress((void**)&woh, g_woh); cudaGetSymbolAddress((void**)&wol, g_wol);
    cudaGetSymbolAddress((void**)&q16, g_q);
    cudaGetSymbolAddress((void**)&kh, g_kh);   cudaGetSymbolAddress((void**)&kl, g_kl);
    cudaGetSymbolAddress((void**)&vh, g_vh);   cudaGetSymbolAddress((void**)&vl, g_vl);
    cudaGetSymbolAddress((void**)&c16, g_c);

    pre_cvt3<<<dim3(Mm, 3), 256>>>((const float4*)query, (const float4*)key, (const float4*)value,
        (uint32_t*)xq, (uint32_t*)xk, (uint32_t*)xv);
    pre_split4<<<dim3(Dd, 4), 256>>>((const float4*)Wq, (const float4*)Wk, (const float4*)Wv, (const float4*)Wo,
        (uint32_t*)wqh, (uint32_t*)wql, (uint32_t*)wkh, (uint32_t*)wkl,
        (uint32_t*)wvh, (uint32_t*)wvl, (uint32_t*)woh, (uint32_t*)wol);

    cudaFuncSetAttribute(gemm_f16x2, cudaFuncAttributeMaxDynamicSharedMemorySize, GSMEM);
    cudaFuncSetAttribute(attn_kernel, cudaFuncAttributeMaxDynamicSharedMemorySize, ASMEM);

    dim3 gGrid(Dd/128, Mm/128);   // (8, 32)
    gemm_f16x2<<<gGrid, 512, GSMEM>>>(xq, wqh, wql, bq, nullptr, (uint32_t*)q16, nullptr, 1);
    gemm_f16x2<<<gGrid, 512, GSMEM>>>(xk, wkh, wkl, bk, nullptr, (uint32_t*)kh, (uint32_t*)kl, 2);
    gemm_f16x2<<<gGrid, 512, GSMEM>>>(xv, wvh, wvl, bv, nullptr, (uint32_t*)vh, (uint32_t*)vl, 2);

    // launch #6 (ncu -s 5 -c 1 captures this one)
    attn_kernel<<<dim3(Ss/128, Hh, Bb), 256, ASMEM>>>(q16, kh, kl, vh, vl,
        (uint32_t*)c16, posr, mask);

    gemm_f16x2<<<gGrid, 512, GSMEM>>>(c16, woh, wol, bo, out, nullptr, nullptr, 0);
}

// round 8
// speedup vs baseline: 3.7771x; 1.0595x over previous
#include <cuda_runtime.h>
#include <cuda_fp16.h>
#include <math.h>
#include <stdint.h>

#define Bb 2
#define Ss 2048
#define Dd 1024
#define Hh 16
#define Mm 4096

// ---------------------------------------------------------------------------
// Scratch (device globals), fp16
// ---------------------------------------------------------------------------
__device__ __half g_xq[Mm*Dd], g_xk[Mm*Dd], g_xv[Mm*Dd];      // inputs, plain
__device__ __half g_wqh[Dd*Dd], g_wql[Dd*Dd];
__device__ __half g_wkh[Dd*Dd], g_wkl[Dd*Dd];
__device__ __half g_wvh[Dd*Dd], g_wvl[Dd*Dd];
__device__ __half g_woh[Dd*Dd], g_wol[Dd*Dd];
__device__ __half g_q[Mm*Dd];                                  // q plain
__device__ __half g_kh[Mm*Dd], g_kl[Mm*Dd];                    // k split
__device__ __half g_vh[Mm*Dd], g_vl[Mm*Dd];                    // v split
__device__ __half g_c[Mm*Dd];                                  // ctx plain
__device__ __half g_pr[(size_t)Bb*Ss*Ss];                      // posr fp16

// ---------------------------------------------------------------------------
// Helpers
// ---------------------------------------------------------------------------
__device__ __forceinline__ uint32_t smem_u32(const void* p) {
    return (uint32_t)__cvta_generic_to_shared(p);
}
__device__ __forceinline__ void cp16(uint32_t dst, const void* src) {
    asm volatile("cp.async.cg.shared.global [%0], [%1], 16;\n" :: "r"(dst), "l"(src));
}
#define CP_COMMIT() asm volatile("cp.async.commit_group;\n" ::: "memory")
template<int N> __device__ __forceinline__ void cp_wait() {
    asm volatile("cp.async.wait_group %0;\n" :: "n"(N) : "memory");
}
__device__ __forceinline__ void ldmx4(uint32_t& r0, uint32_t& r1, uint32_t& r2, uint32_t& r3, uint32_t a) {
    asm volatile("ldmatrix.sync.aligned.m8n8.x4.shared.b16 {%0,%1,%2,%3}, [%4];\n"
        : "=r"(r0), "=r"(r1), "=r"(r2), "=r"(r3) : "r"(a));
}
__device__ __forceinline__ void ldmx4t(uint32_t& r0, uint32_t& r1, uint32_t& r2, uint32_t& r3, uint32_t a) {
    asm volatile("ldmatrix.sync.aligned.m8n8.x4.trans.shared.b16 {%0,%1,%2,%3}, [%4];\n"
        : "=r"(r0), "=r"(r1), "=r"(r2), "=r"(r3) : "r"(a));
}
__device__ __forceinline__ void mma16816(float* c, uint32_t a0, uint32_t a1, uint32_t a2, uint32_t a3,
                                         uint32_t b0, uint32_t b1) {
    asm volatile("mma.sync.aligned.m16n8k16.row.col.f32.f16.f16.f32 "
        "{%0,%1,%2,%3}, {%4,%5,%6,%7}, {%8,%9}, {%0,%1,%2,%3};\n"
        : "+f"(c[0]), "+f"(c[1]), "+f"(c[2]), "+f"(c[3])
        : "r"(a0), "r"(a1), "r"(a2), "r"(a3), "r"(b0), "r"(b1));
}
__device__ __forceinline__ uint32_t pack_h(float e0, float e1) {
    union { __half2 v; uint32_t u; } t;
    t.v = __floats2half2_rn(e0, e1);
    return t.u;
}
__device__ __forceinline__ float lo_h(uint32_t p) {
    union { uint32_t u; __half2 v; } t; t.u = p; return __low2float(t.v);
}
__device__ __forceinline__ float hi_h(uint32_t p) {
    union { uint32_t u; __half2 v; } t; t.u = p; return __high2float(t.v);
}
__device__ __forceinline__ float2 h2f2(uint32_t p) {
    union { uint32_t u; __half2 v; } t; t.u = p; return __half22float2(t.v);
}

// exp on the FMA pipe (no MUFU)
__device__ __forceinline__ float fast_exp(float x) {
    x = fmaxf(x, -80.0f);
    float y  = x * 1.4426950408889634f;
    float rr = y + 12582912.0f;
    float n  = rr - 12582912.0f;
    float f  = y - n;
    float p  = 1.3333558e-3f;
    p = fmaf(p, f, 9.6181291e-3f);
    p = fmaf(p, f, 5.5504109e-2f);
    p = fmaf(p, f, 2.4022651e-1f);
    p = fmaf(p, f, 6.9314718e-1f);
    p = fmaf(p, f, 1.0f);
    int e = __float_as_int(rr) - 0x4B400000;
    float s = __int_as_float((e + 127) << 23);
    return p * s;
}

// swizzled smem byte offset within a tile of 128B rows (8 chunks of 16B)
__device__ __forceinline__ uint32_t swz(int row, int chunk) {
    return (uint32_t)(row * 128 + ((chunk ^ (row & 7)) << 4));
}

// ---------------------------------------------------------------------------
// Preprocess
// ---------------------------------------------------------------------------
__global__ void pre_cvt3(const float4* __restrict__ A, const float4* __restrict__ B,
                         const float4* __restrict__ C,
                         uint32_t* __restrict__ Ao, uint32_t* __restrict__ Bo,
                         uint32_t* __restrict__ Co)
{
    int idx = blockIdx.x * 256 + threadIdx.x;
    const float4* X = (blockIdx.y == 0) ? A : (blockIdx.y == 1) ? B : C;
    uint32_t*     Y = (blockIdx.y == 0) ? Ao : (blockIdx.y == 1) ? Bo : Co;
    float4 v = X[idx];
    Y[idx*2]   = pack_h(v.x, v.y);
    Y[idx*2+1] = pack_h(v.z, v.w);
}

__global__ void pre_posr(const float4* __restrict__ P, uint32_t* __restrict__ Po)
{
    int idx = blockIdx.x * 256 + threadIdx.x;   // 2M float4
    float4 v = P[idx];
    Po[idx*2]   = pack_h(v.x, v.y);
    Po[idx*2+1] = pack_h(v.z, v.w);
}

__device__ __forceinline__ void split_one(const float4* __restrict__ X,
                                          uint32_t* __restrict__ Xh, uint32_t* __restrict__ Xl)
{
    int idx = blockIdx.x * 256 + threadIdx.x;
    float4 v = X[idx];
    uint32_t h0 = pack_h(v.x, v.y);
    uint32_t l0 = pack_h(v.x - lo_h(h0), v.y - hi_h(h0));
    uint32_t h1 = pack_h(v.z, v.w);
    uint32_t l1 = pack_h(v.z - lo_h(h1), v.w - hi_h(h1));
    Xh[idx*2]   = h0;  Xh[idx*2+1] = h1;
    Xl[idx*2]   = l0;  Xl[idx*2+1] = l1;
}

__global__ void pre_split4(const float4* __restrict__ A, const float4* __restrict__ B,
                           const float4* __restrict__ C, const float4* __restrict__ D,
                           uint32_t* __restrict__ Ah, uint32_t* __restrict__ Al,
                           uint32_t* __restrict__ Bh, uint32_t* __restrict__ Bl,
                           uint32_t* __restrict__ Ch, uint32_t* __restrict__ Cl,
                           uint32_t* __restrict__ Dh, uint32_t* __restrict__ Dl)
{
    if (blockIdx.y == 0)      split_one(A, Ah, Al);
    else if (blockIdx.y == 1) split_one(B, Bh, Bl);
    else if (blockIdx.y == 2) split_one(C, Ch, Cl);
    else                      split_one(D, Dh, Dl);
}

// ---------------------------------------------------------------------------
// fp16 2-pass GEMM: C[4096,1024] = A @ (Wh+Wl)^T + bias
// BM=256 BN=128 BK=64, 3-stage cp.async, 16 warps (4m x 4n), warp 64x32.
// Grid (8, 16) = 128 CTAs -> single wave.
// outMode: 0 = fp32, 1 = plain fp16, 2 = split fp16 (hi/lo)
// ---------------------------------------------------------------------------
#define GST 65536                    // stage: A 32K | Wh 16K | Wl 16K
#define GSMEM (3*GST)                // 196608

__device__ __forceinline__ void gemm_load_stage(uint32_t base,
    const __half* A, const __half* Wh, const __half* Wl,
    int m0, int n0, int k0, int tid)
{
#pragma unroll
    for (int i = 0; i < 4; i++) {                 // A: 256 rows x 8 chunks
        int idx = tid + i * 512;                  // 0..2047
        int r = idx >> 3, c = idx & 7;
        cp16(base + swz(r, c), A + (size_t)(m0 + r) * Dd + k0 + c * 8);
    }
#pragma unroll
    for (int i = 0; i < 2; i++) {                 // W: 128 rows x 8 chunks
        int idx = tid + i * 512;                  // 0..1023
        int r = idx >> 3, c = idx & 7;
        uint32_t so = swz(r, c);
        cp16(base + 32768 + so, Wh + (size_t)(n0 + r) * Dd + k0 + c * 8);
        cp16(base + 49152 + so, Wl + (size_t)(n0 + r) * Dd + k0 + c * 8);
    }
}

__global__ __launch_bounds__(512) void gemm_f16x2(
    const __half* __restrict__ A,
    const __half* __restrict__ Wh, const __half* __restrict__ Wl,
    const float* __restrict__ bias,
    float* __restrict__ Cf, uint32_t* __restrict__ Co, uint32_t* __restrict__ Col,
    int outMode)
{
    extern __shared__ __align__(16) char sm[];
    const uint32_t smb = smem_u32(sm);
    const int tid = threadIdx.x, wid = tid >> 5, lane = tid & 31;
    const int m0 = blockIdx.y * 256, n0 = blockIdx.x * 128;
    const int wm = wid >> 2, wn = wid & 3;           // 4 x 4 warp grid, warp 64x32
    const int sub = lane >> 3, lr = lane & 7;

    float acc[4][4][4];
#pragma unroll
    for (int a = 0; a < 4; a++)
#pragma unroll
        for (int b = 0; b < 4; b++)
#pragma unroll
            for (int c = 0; c < 4; c++) acc[a][b][c] = 0.f;

    gemm_load_stage(smb,       A, Wh, Wl, m0, n0, 0,  tid); CP_COMMIT();
    gemm_load_stage(smb + GST, A, Wh, Wl, m0, n0, 64, tid); CP_COMMIT();

    for (int it = 0; it < 16; it++) {
        if (it + 2 < 16) {
            gemm_load_stage(smb + ((it+2)%3)*GST, A, Wh, Wl, m0, n0, (it+2)*64, tid);
            CP_COMMIT();
            cp_wait<2>();
        } else {
            cp_wait<0>();
        }
        __syncthreads();
        uint32_t stg = smb + (it%3)*GST;

#pragma unroll
        for (int ks = 0; ks < 4; ks++) {
            int ch = 2*ks + (sub >> 1);
            uint32_t ah[4][4];
#pragma unroll
            for (int mt = 0; mt < 4; mt++) {
                int row = wm*64 + mt*16 + lr + (sub & 1)*8;
                ldmx4(ah[mt][0], ah[mt][1], ah[mt][2], ah[mt][3], stg + swz(row, ch));
            }
            uint32_t bh[8], bl[8];   // [p pair: tiles 2p, 2p+1]
#pragma unroll
            for (int p = 0; p < 2; p++) {
                int row = wn*32 + p*16 + lr + (sub & 1)*8;
                uint32_t so = swz(row, ch);
                ldmx4(bh[p*4+0], bh[p*4+1], bh[p*4+2], bh[p*4+3], stg + 32768 + so);
                ldmx4(bl[p*4+0], bl[p*4+1], bl[p*4+2], bl[p*4+3], stg + 49152 + so);
            }
            // pass 1: a x Wh  (16 independent MMAs)
#pragma unroll
            for (int mt = 0; mt < 4; mt++)
#pragma unroll
                for (int p = 0; p < 2; p++) {
                    mma16816(acc[mt][2*p],   ah[mt][0],ah[mt][1],ah[mt][2],ah[mt][3], bh[p*4+0], bh[p*4+2]);
                    mma16816(acc[mt][2*p+1], ah[mt][0],ah[mt][1],ah[mt][2],ah[mt][3], bh[p*4+1], bh[p*4+3]);
                }
            // pass 2: a x Wl
#pragma unroll
            for (int mt = 0; mt < 4; mt++)
#pragma unroll
                for (int p = 0; p < 2; p++) {
                    mma16816(acc[mt][2*p],   ah[mt][0],ah[mt][1],ah[mt][2],ah[mt][3], bl[p*4+0], bl[p*4+2]);
                    mma16816(acc[mt][2*p+1], ah[mt][0],ah[mt][1],ah[mt][2],ah[mt][3], bl[p*4+1], bl[p*4+3]);
                }
        }
        __syncthreads();
    }

    // Epilogue
#pragma unroll
    for (int mt = 0; mt < 4; mt++) {
#pragma unroll
        for (int nt = 0; nt < 4; nt++) {
            int gr = m0 + wm*64 + mt*16 + (lane >> 2);
            int gc = n0 + wn*32 + nt*8 + (lane & 3)*2;
            float b0 = bias[gc], b1 = bias[gc+1];
            float v0 = acc[mt][nt][0] + b0, v1 = acc[mt][nt][1] + b1;
            float v2 = acc[mt][nt][2] + b0, v3 = acc[mt][nt][3] + b1;
            if (outMode == 0) {
                *(float2*)(Cf + (size_t)gr*Dd + gc)     = make_float2(v0, v1);
                *(float2*)(Cf + (size_t)(gr+8)*Dd + gc) = make_float2(v2, v3);
            } else if (outMode == 1) {
                Co[(size_t)gr*512 + (gc>>1)]     = pack_h(v0, v1);
                Co[(size_t)(gr+8)*512 + (gc>>1)] = pack_h(v2, v3);
            } else {
                uint32_t h0 = pack_h(v0, v1);
                uint32_t l0 = pack_h(v0 - lo_h(h0), v1 - hi_h(h0));
                uint32_t h1 = pack_h(v2, v3);
                uint32_t l1 = pack_h(v2 - lo_h(h1), v3 - hi_h(h1));
                Co[(size_t)gr*512 + (gc>>1)]      = h0;
                Col[(size_t)gr*512 + (gc>>1)]     = l0;
                Co[(size_t)(gr+8)*512 + (gc>>1)]  = h1;
                Col[(size_t)(gr+8)*512 + (gc>>1)] = l1;
            }
        }
    }
}

// ---------------------------------------------------------------------------
// Flash attention, fp16 2-pass. CTA = 128 q-rows of one (b,h). 8 warps.
// Q plain fp16; K,V split hi/lo; posr fp16. K/V double-buffered.
// ---------------------------------------------------------------------------
#define AQ 0
#define AKV 16384              // stage: KH | KL(+8192) | VH(+16384) | VL(+24576)
#define AKVST 32768
#define ASMEM (AKV + 2*AKVST)  // 81920

__device__ __forceinline__ void attn_load_kv(uint32_t base,
    const __half* Kh, const __half* Kl, const __half* Vh, const __half* Vl,
    size_t rowBase, int headOff, int k0, int tid)
{
#pragma unroll
    for (int i = 0; i < 2; i++) {
        int idx = tid + i * 256;          // 0..511 : 64 rows x 8 chunks
        int r = idx >> 3, c = idx & 7;
        uint32_t so = swz(r, c);
        size_t g = (rowBase + k0 + r) * Dd + headOff + c * 8;
        cp16(base + so,         Kh + g);
        cp16(base + 8192 + so,  Kl + g);
        cp16(base + 16384 + so, Vh + g);
        cp16(base + 24576 + so, Vl + g);
    }
}

__global__ __launch_bounds__(256, 2) void attn_kernel(
    const __half* __restrict__ Q,
    const __half* __restrict__ Kh, const __half* __restrict__ Kl,
    const __half* __restrict__ Vh, const __half* __restrict__ Vl,
    uint32_t* __restrict__ Co,
    const __half* __restrict__ posr, const int* __restrict__ mask)
{
    extern __shared__ __align__(16) char sm[];
    const uint32_t smb = smem_u32(sm);
    const int tid = threadIdx.x, wid = tid >> 5, lane = tid & 31;
    const int sub = lane >> 3, lr = lane & 7;
    const int q0 = blockIdx.x * 128;
    const int h  = blockIdx.y;
    const int b  = blockIdx.z;
    const int headOff = h * 64;
    const size_t rowBase = (size_t)b * Ss;

    // load Q tile (128 x 64 fp16)
#pragma unroll
    for (int i = 0; i < 4; i++) {
        int idx = tid + i * 256;          // 0..1023
        int r = idx >> 3, c = idx & 7;
        cp16(smb + AQ + swz(r, c), Q + (rowBase + q0 + r) * Dd + headOff + c * 8);
    }
    attn_load_kv(smb + AKV, Kh, Kl, Vh, Vl, rowBase, headOff, 0, tid);
    CP_COMMIT();
    cp_wait<0>();
    __syncthreads();

    // preload Q fragments (warp-owned rows fixed)
    uint32_t qf[4][4];
#pragma unroll
    for (int ks = 0; ks < 4; ks++) {
        int row = wid*16 + lr + (sub & 1)*8;
        int ch  = 2*ks + (sub >> 1);
        ldmx4(qf[ks][0], qf[ks][1], qf[ks][2], qf[ks][3], smb + AQ + swz(row, ch));
    }

    float o[8][4];
#pragma unroll
    for (int i = 0; i < 8; i++)
#pragma unroll
        for (int j = 0; j < 4; j++) o[i][j] = 0.f;
    float mrow[2] = {-1e30f, -1e30f};
    float lrow[2] = {0.f, 0.f};

    const int r_lo = q0 + wid*16 + (lane >> 2);
    const int r_hi = r_lo + 8;
    const __half* prLo = posr + ((size_t)b*Ss + r_lo)*Ss;
    const __half* prHi = posr + ((size_t)b*Ss + r_hi)*Ss;
    const int*    mkB  = mask + b*Ss;

    for (int kt = 0; kt < 32; kt++) {
        uint32_t stg = smb + AKV + (kt & 1) * AKVST;
        if (kt + 1 < 32) {
            attn_load_kv(smb + AKV + ((kt+1) & 1) * AKVST, Kh, Kl, Vh, Vl,
                         rowBase, headOff, (kt+1)*64, tid);
            CP_COMMIT();
            cp_wait<1>();
        } else {
            cp_wait<0>();
        }
        __syncthreads();

        // ---- S = Q @ K^T (fp16 2-pass, interleaved MMA pairs) ----
        float s[8][4];
#pragma unroll
        for (int i = 0; i < 8; i++)
#pragma unroll
            for (int j = 0; j < 4; j++) s[i][j] = 0.f;

#pragma unroll
        for (int ks = 0; ks < 4; ks++) {
#pragma unroll
            for (int p = 0; p < 4; p++) {    // pairs of n-tiles (2p, 2p+1)
                int row = p*16 + lr + (sub & 1)*8;
                int ch  = 2*ks + (sub >> 1);
                uint32_t so = swz(row, ch);
                uint32_t kh4[4], kl4[4];
                ldmx4(kh4[0], kh4[1], kh4[2], kh4[3], stg + so);
                ldmx4(kl4[0], kl4[1], kl4[2], kl4[3], stg + 8192 + so);
                mma16816(s[2*p],   qf[ks][0],qf[ks][1],qf[ks][2],qf[ks][3], kh4[0], kh4[2]);
                mma16816(s[2*p+1], qf[ks][0],qf[ks][1],qf[ks][2],qf[ks][3], kh4[1], kh4[3]);
                mma16816(s[2*p],   qf[ks][0],qf[ks][1],qf[ks][2],qf[ks][3], kl4[0], kl4[2]);
                mma16816(s[2*p+1], qf[ks][0],qf[ks][1],qf[ks][2],qf[ks][3], kl4[1], kl4[3]);
            }
        }

        // ---- scale + posr(fp16) + mask ----
        const int colB = kt*64 + (lane & 3)*2;
#pragma unroll
        for (int nt = 0; nt < 8; nt++) {
            int col = colB + nt*8;
            int2 mk = *(const int2*)(mkB + col);
            float2 p0 = h2f2(*(const uint32_t*)(prLo + col));
            float2 p1 = h2f2(*(const uint32_t*)(prHi + col));
            s[nt][0] = (mk.x != 0) ? fmaf(s[nt][0], 0.125f, p0.x) : -1e9f;
            s[nt][1] = (mk.y != 0) ? fmaf(s[nt][1], 0.125f, p0.y) : -1e9f;
            s[nt][2] = (mk.x != 0) ? fmaf(s[nt][2], 0.125f, p1.x) : -1e9f;
            s[nt][3] = (mk.y != 0) ? fmaf(s[nt][3], 0.125f, p1.y) : -1e9f;
        }

        // ---- online softmax ----
        float tm0 = -1e30f, tm1 = -1e30f;
#pragma unroll
        for (int nt = 0; nt < 8; nt++) {
            tm0 = fmaxf(tm0, fmaxf(s[nt][0], s[nt][1]));
            tm1 = fmaxf(tm1, fmaxf(s[nt][2], s[nt][3]));
        }
        tm0 = fmaxf(tm0, __shfl_xor_sync(0xffffffffu, tm0, 1));
        tm0 = fmaxf(tm0, __shfl_xor_sync(0xffffffffu, tm0, 2));
        tm1 = fmaxf(tm1, __shfl_xor_sync(0xffffffffu, tm1, 1));
        tm1 = fmaxf(tm1, __shfl_xor_sync(0xffffffffu, tm1, 2));

        float mn0 = fmaxf(mrow[0], tm0), mn1 = fmaxf(mrow[1], tm1);
        float f0 = fast_exp(mrow[0] - mn0), f1 = fast_exp(mrow[1] - mn1);
        mrow[0] = mn0; mrow[1] = mn1;

        float sum0 = 0.f, sum1 = 0.f;
#pragma unroll
        for (int nt = 0; nt < 8; nt++) {
            s[nt][0] = fast_exp(s[nt][0] - mn0);
            s[nt][1] = fast_exp(s[nt][1] - mn0);
            s[nt][2] = fast_exp(s[nt][2] - mn1);
            s[nt][3] = fast_exp(s[nt][3] - mn1);
            sum0 += s[nt][0] + s[nt][1];
            sum1 += s[nt][2] + s[nt][3];
        }
        sum0 += __shfl_xor_sync(0xffffffffu, sum0, 1);
        sum0 += __shfl_xor_sync(0xffffffffu, sum0, 2);
        sum1 += __shfl_xor_sync(0xffffffffu, sum1, 1);
        sum1 += __shfl_xor_sync(0xffffffffu, sum1, 2);
        lrow[0] = lrow[0] * f0 + sum0;
        lrow[1] = lrow[1] * f1 + sum1;

#pragma unroll
        for (int nt2 = 0; nt2 < 8; nt2++) {
            o[nt2][0] *= f0; o[nt2][1] *= f0;
            o[nt2][2] *= f1; o[nt2][3] *= f1;
        }

        // ---- pack P (plain fp16) into A-frags; acc += P @ (Vh+Vl) ----
#pragma unroll
        for (int ks = 0; ks < 4; ks++) {
            int t0 = 2*ks, t1 = 2*ks + 1;
            uint32_t ph0 = pack_h(s[t0][0], s[t0][1]);
            uint32_t ph1 = pack_h(s[t0][2], s[t0][3]);
            uint32_t ph2 = pack_h(s[t1][0], s[t1][1]);
            uint32_t ph3 = pack_h(s[t1][2], s[t1][3]);
            int row = ks*16 + (lane & 15);
#pragma unroll
            for (int np = 0; np < 4; np++) {   // pairs of d-tiles (2np, 2np+1)
                uint32_t so = swz(row, np*2 + (lane >> 4));
                uint32_t h0,h1,h2,h3, l0,l1,l2,l3;
                ldmx4t(h0,h1,h2,h3, stg + 16384 + so);
                ldmx4t(l0,l1,l2,l3, stg + 24576 + so);
                mma16816(o[2*np],   ph0,ph1,ph2,ph3, h0,h1);
                mma16816(o[2*np+1], ph0,ph1,ph2,ph3, h2,h3);
                mma16816(o[2*np],   ph0,ph1,ph2,ph3, l0,l1);
                mma16816(o[2*np+1], ph0,ph1,ph2,ph3, l2,l3);
            }
        }
        __syncthreads();
    }

    // ---- epilogue: normalize, write ctx (plain fp16) ----
    float inv0 = 1.f / lrow[0], inv1 = 1.f / lrow[1];
    const size_t grLo = rowBase + (size_t)r_lo;
    const size_t grHi = rowBase + (size_t)r_hi;
#pragma unroll
    for (int nt2 = 0; nt2 < 8; nt2++) {
        int gc = headOff + nt2*8 + (lane & 3)*2;
        Co[grLo*512 + (gc>>1)] = pack_h(o[nt2][0] * inv0, o[nt2][1] * inv0);
        Co[grHi*512 + (gc>>1)] = pack_h(o[nt2][2] * inv1, o[nt2][3] * inv1);
    }
}

// ---------------------------------------------------------------------------
extern "C" void kernel_launch(void* const* d_in, const int* in_sizes, int n_in,
                              void* d_out, int out_size)
{
    const float* query = (const float*)d_in[0];
    const float* key   = (const float*)d_in[1];
    const float* value = (const float*)d_in[2];
    const int*   mask  = (const int*)  d_in[3];
    const float* posr  = (const float*)d_in[4];
    const float* Wq    = (const float*)d_in[5];
    const float* bq    = (const float*)d_in[6];
    const float* Wk    = (const float*)d_in[7];
    const float* bk    = (const float*)d_in[8];
    const float* Wv    = (const float*)d_in[9];
    const float* bv    = (const float*)d_in[10];
    const float* Wo    = (const float*)d_in[11];
    const float* bo    = (const float*)d_in[12];
    float* out = (float*)d_out;

    __half *xq,*xk,*xv, *q16, *kh,*kl, *vh,*vl, *c16, *pr16;
    __half *wqh,*wql,*wkh,*wkl,*wvh,*wvl,*woh,*wol;
    cudaGetSymbolAddress((void**)&xq, g_xq);   cudaGetSymbolAddress((void**)&xk, g_xk);
    cudaGetSymbolAddress((void**)&xv, g_xv);
    cudaGetSymbolAddress((void**)&wqh, g_wqh); cudaGetSymbolAddress((void**)&wql, g_wql);
    cudaGetSymbolAddress((void**)&wkh, g_wkh); cudaGetSymbolAddress((void**)&wkl, g_wkl);
    cudaGetSymbolAddress((void**)&wvh, g_wvh); cudaGetSymbolAddress((void**)&wvl, g_wvl);
    cudaGetSymbolAddress((void**)&woh, g_woh); cudaGetSymbolAddress((void**)&wol, g_wol);
    cudaGetSymbolAddress((void**)&q16, g_q);
    cudaGetSymbolAddress((void**)&kh, g_kh);   cudaGetSymbolAddress((void**)&kl, g_kl);
    cudaGetSymbolAddress((void**)&vh, g_vh);   cudaGetSymbolAddress((void**)&vl, g_vl);
    cudaGetSymbolAddress((void**)&c16, g_c);
    cudaGetSymbolAddress((void**)&pr16, g_pr);

    pre_cvt3<<<dim3(Mm, 3), 256>>>((const float4*)query, (const float4*)key, (const float4*)value,
        (uint32_t*)xq, (uint32_t*)xk, (uint32_t*)xv);
    pre_posr<<<(Bb*Ss*Ss/4)/256, 256>>>((const float4*)posr, (uint32_t*)pr16);
    pre_split4<<<dim3(Dd, 4), 256>>>((const float4*)Wq, (const float4*)Wk, (const float4*)Wv, (const float4*)Wo,
        (uint32_t*)wqh, (uint32_t*)wql, (uint32_t*)wkh, (uint32_t*)wkl,
        (uint32_t*)wvh, (uint32_t*)wvl, (uint32_t*)woh, (uint32_t*)wol);

    cudaFuncSetAttribute(gemm_f16x2, cudaFuncAttributeMaxDynamicSharedMemorySize, GSMEM);
    cudaFuncSetAttribute(attn_kernel, cudaFuncAttributeMaxDynamicSharedMemorySize, ASMEM);

    dim3 gGrid(Dd/128, Mm/256);   // (8, 16) = 128 CTAs
    gemm_f16x2<<<gGrid, 512, GSMEM>>>(xq, wqh, wql, bq, nullptr, (uint32_t*)q16, nullptr, 1);
    gemm_f16x2<<<gGrid, 512, GSMEM>>>(xk, wkh, wkl, bk, nullptr, (uint32_t*)kh, (uint32_t*)kl, 2);
    gemm_f16x2<<<gGrid, 512, GSMEM>>>(xv, wvh, wvl, bv, nullptr, (uint32_t*)vh, (uint32_t*)vl, 2);

    attn_kernel<<<dim3(Ss/128, Hh, Bb), 256, ASMEM>>>(q16, kh, kl, vh, vl,
        (uint32_t*)c16, pr16, mask);

    gemm_f16x2<<<gGrid, 512, GSMEM>>>(c16, woh, wol, bo, out, nullptr, nullptr, 0);
}

// round 9
// speedup vs baseline: 4.2242x; 1.1184x over previous
#include <cuda_runtime.h>
#include <cuda_fp16.h>
#include <math.h>
#include <stdint.h>

#define Bb 2
#define Ss 2048
#define Dd 1024
#define Hh 16
#define Mm 4096

// ---------------------------------------------------------------------------
// Scratch (device globals), fp16
// ---------------------------------------------------------------------------
__device__ __half g_xq[Mm*Dd], g_xk[Mm*Dd], g_xv[Mm*Dd];      // inputs, plain
__device__ __half g_wqh[Dd*Dd], g_wql[Dd*Dd];
__device__ __half g_wkh[Dd*Dd], g_wkl[Dd*Dd];
__device__ __half g_wvh[Dd*Dd], g_wvl[Dd*Dd];
__device__ __half g_woh[Dd*Dd], g_wol[Dd*Dd];
__device__ __half g_q[Mm*Dd], g_k[Mm*Dd], g_v[Mm*Dd];          // q,k,v plain
__device__ __half g_c[Mm*Dd];                                  // ctx plain

// ---------------------------------------------------------------------------
// Helpers
// ---------------------------------------------------------------------------
__device__ __forceinline__ uint32_t smem_u32(const void* p) {
    return (uint32_t)__cvta_generic_to_shared(p);
}
__device__ __forceinline__ void cp16(uint32_t dst, const void* src) {
    asm volatile("cp.async.cg.shared.global [%0], [%1], 16;\n" :: "r"(dst), "l"(src));
}
#define CP_COMMIT() asm volatile("cp.async.commit_group;\n" ::: "memory")
template<int N> __device__ __forceinline__ void cp_wait() {
    asm volatile("cp.async.wait_group %0;\n" :: "n"(N) : "memory");
}
__device__ __forceinline__ void ldmx4(uint32_t& r0, uint32_t& r1, uint32_t& r2, uint32_t& r3, uint32_t a) {
    asm volatile("ldmatrix.sync.aligned.m8n8.x4.shared.b16 {%0,%1,%2,%3}, [%4];\n"
        : "=r"(r0), "=r"(r1), "=r"(r2), "=r"(r3) : "r"(a));
}
__device__ __forceinline__ void ldmx4t(uint32_t& r0, uint32_t& r1, uint32_t& r2, uint32_t& r3, uint32_t a) {
    asm volatile("ldmatrix.sync.aligned.m8n8.x4.trans.shared.b16 {%0,%1,%2,%3}, [%4];\n"
        : "=r"(r0), "=r"(r1), "=r"(r2), "=r"(r3) : "r"(a));
}
__device__ __forceinline__ void mma16816(float* c, uint32_t a0, uint32_t a1, uint32_t a2, uint32_t a3,
                                         uint32_t b0, uint32_t b1) {
    asm volatile("mma.sync.aligned.m16n8k16.row.col.f32.f16.f16.f32 "
        "{%0,%1,%2,%3}, {%4,%5,%6,%7}, {%8,%9}, {%0,%1,%2,%3};\n"
        : "+f"(c[0]), "+f"(c[1]), "+f"(c[2]), "+f"(c[3])
        : "r"(a0), "r"(a1), "r"(a2), "r"(a3), "r"(b0), "r"(b1));
}
__device__ __forceinline__ uint32_t pack_h(float e0, float e1) {
    union { __half2 v; uint32_t u; } t;
    t.v = __floats2half2_rn(e0, e1);
    return t.u;
}
__device__ __forceinline__ float lo_h(uint32_t p) {
    union { uint32_t u; __half2 v; } t; t.u = p; return __low2float(t.v);
}
__device__ __forceinline__ float hi_h(uint32_t p) {
    union { uint32_t u; __half2 v; } t; t.u = p; return __high2float(t.v);
}

// exp on the FMA pipe (no MUFU)
__device__ __forceinline__ float fast_exp(float x) {
    x = fmaxf(x, -80.0f);
    float y  = x * 1.4426950408889634f;
    float rr = y + 12582912.0f;
    float n  = rr - 12582912.0f;
    float f  = y - n;
    float p  = 1.3333558e-3f;
    p = fmaf(p, f, 9.6181291e-3f);
    p = fmaf(p, f, 5.5504109e-2f);
    p = fmaf(p, f, 2.4022651e-1f);
    p = fmaf(p, f, 6.9314718e-1f);
    p = fmaf(p, f, 1.0f);
    int e = __float_as_int(rr) - 0x4B400000;
    float s = __int_as_float((e + 127) << 23);
    return p * s;
}

// swizzled smem byte offset within a tile of 128B rows (8 chunks of 16B)
__device__ __forceinline__ uint32_t swz(int row, int chunk) {
    return (uint32_t)(row * 128 + ((chunk ^ (row & 7)) << 4));
}

// ---------------------------------------------------------------------------
// Preprocess
// ---------------------------------------------------------------------------
__global__ void pre_cvt3(const float4* __restrict__ A, const float4* __restrict__ B,
                         const float4* __restrict__ C,
                         uint32_t* __restrict__ Ao, uint32_t* __restrict__ Bo,
                         uint32_t* __restrict__ Co)
{
    int idx = blockIdx.x * 256 + threadIdx.x;
    const float4* X = (blockIdx.y == 0) ? A : (blockIdx.y == 1) ? B : C;
    uint32_t*     Y = (blockIdx.y == 0) ? Ao : (blockIdx.y == 1) ? Bo : Co;
    float4 v = X[idx];
    Y[idx*2]   = pack_h(v.x, v.y);
    Y[idx*2+1] = pack_h(v.z, v.w);
}

__device__ __forceinline__ void split_one(const float4* __restrict__ X,
                                          uint32_t* __restrict__ Xh, uint32_t* __restrict__ Xl)
{
    int idx = blockIdx.x * 256 + threadIdx.x;
    float4 v = X[idx];
    uint32_t h0 = pack_h(v.x, v.y);
    uint32_t l0 = pack_h(v.x - lo_h(h0), v.y - hi_h(h0));
    uint32_t h1 = pack_h(v.z, v.w);
    uint32_t l1 = pack_h(v.z - lo_h(h1), v.w - hi_h(h1));
    Xh[idx*2]   = h0;  Xh[idx*2+1] = h1;
    Xl[idx*2]   = l0;  Xl[idx*2+1] = l1;
}

__global__ void pre_split4(const float4* __restrict__ A, const float4* __restrict__ B,
                           const float4* __restrict__ C, const float4* __restrict__ D,
                           uint32_t* __restrict__ Ah, uint32_t* __restrict__ Al,
                           uint32_t* __restrict__ Bh, uint32_t* __restrict__ Bl,
                           uint32_t* __restrict__ Ch, uint32_t* __restrict__ Cl,
                           uint32_t* __restrict__ Dh, uint32_t* __restrict__ Dl)
{
    if (blockIdx.y == 0)      split_one(A, Ah, Al);
    else if (blockIdx.y == 1) split_one(B, Bh, Bl);
    else if (blockIdx.y == 2) split_one(C, Ch, Cl);
    else                      split_one(D, Dh, Dl);
}

// ---------------------------------------------------------------------------
// fp16 2-pass GEMM: C[4096,1024] = A @ (Wh+Wl)^T + bias
// BM=256 BN=128 BK=64, 3-stage cp.async, 16 warps (4m x 4n), warp 64x32.
// Grid (8, 16) = 128 CTAs -> single wave.
// outMode: 0 = fp32, 1 = plain fp16
// ---------------------------------------------------------------------------
#define GST 65536                    // stage: A 32K | Wh 16K | Wl 16K
#define GSMEM (3*GST)                // 196608

__device__ __forceinline__ void gemm_load_stage(uint32_t base,
    const __half* A, const __half* Wh, const __half* Wl,
    int m0, int n0, int k0, int tid)
{
#pragma unroll
    for (int i = 0; i < 4; i++) {                 // A: 256 rows x 8 chunks
        int idx = tid + i * 512;                  // 0..2047
        int r = idx >> 3, c = idx & 7;
        cp16(base + swz(r, c), A + (size_t)(m0 + r) * Dd + k0 + c * 8);
    }
#pragma unroll
    for (int i = 0; i < 2; i++) {                 // W: 128 rows x 8 chunks
        int idx = tid + i * 512;                  // 0..1023
        int r = idx >> 3, c = idx & 7;
        uint32_t so = swz(r, c);
        cp16(base + 32768 + so, Wh + (size_t)(n0 + r) * Dd + k0 + c * 8);
        cp16(base + 49152 + so, Wl + (size_t)(n0 + r) * Dd + k0 + c * 8);
    }
}

__global__ __launch_bounds__(512) void gemm_f16x2(
    const __half* __restrict__ A,
    const __half* __restrict__ Wh, const __half* __restrict__ Wl,
    const float* __restrict__ bias,
    float* __restrict__ Cf, uint32_t* __restrict__ Co,
    int outMode)
{
    extern __shared__ __align__(16) char sm[];
    const uint32_t smb = smem_u32(sm);
    const int tid = threadIdx.x, wid = tid >> 5, lane = tid & 31;
    const int m0 = blockIdx.y * 256, n0 = blockIdx.x * 128;
    const int wm = wid >> 2, wn = wid & 3;           // 4 x 4 warp grid, warp 64x32
    const int sub = lane >> 3, lr = lane & 7;

    float acc[4][4][4];
#pragma unroll
    for (int a = 0; a < 4; a++)
#pragma unroll
        for (int b = 0; b < 4; b++)
#pragma unroll
            for (int c = 0; c < 4; c++) acc[a][b][c] = 0.f;

    gemm_load_stage(smb,       A, Wh, Wl, m0, n0, 0,  tid); CP_COMMIT();
    gemm_load_stage(smb + GST, A, Wh, Wl, m0, n0, 64, tid); CP_COMMIT();

    for (int it = 0; it < 16; it++) {
        if (it + 2 < 16) {
            gemm_load_stage(smb + ((it+2)%3)*GST, A, Wh, Wl, m0, n0, (it+2)*64, tid);
            CP_COMMIT();
            cp_wait<2>();
        } else {
            cp_wait<0>();
        }
        __syncthreads();
        uint32_t stg = smb + (it%3)*GST;

#pragma unroll
        for (int ks = 0; ks < 4; ks++) {
            int ch = 2*ks + (sub >> 1);
            uint32_t ah[4][4];
#pragma unroll
            for (int mt = 0; mt < 4; mt++) {
                int row = wm*64 + mt*16 + lr + (sub & 1)*8;
                ldmx4(ah[mt][0], ah[mt][1], ah[mt][2], ah[mt][3], stg + swz(row, ch));
            }
            uint32_t bh[8], bl[8];   // [p pair: tiles 2p, 2p+1]
#pragma unroll
            for (int p = 0; p < 2; p++) {
                int row = wn*32 + p*16 + lr + (sub & 1)*8;
                uint32_t so = swz(row, ch);
                ldmx4(bh[p*4+0], bh[p*4+1], bh[p*4+2], bh[p*4+3], stg + 32768 + so);
                ldmx4(bl[p*4+0], bl[p*4+1], bl[p*4+2], bl[p*4+3], stg + 49152 + so);
            }
            // pass 1: a x Wh  (16 independent MMAs)
#pragma unroll
            for (int mt = 0; mt < 4; mt++)
#pragma unroll
                for (int p = 0; p < 2; p++) {
                    mma16816(acc[mt][2*p],   ah[mt][0],ah[mt][1],ah[mt][2],ah[mt][3], bh[p*4+0], bh[p*4+2]);
                    mma16816(acc[mt][2*p+1], ah[mt][0],ah[mt][1],ah[mt][2],ah[mt][3], bh[p*4+1], bh[p*4+3]);
                }
            // pass 2: a x Wl
#pragma unroll
            for (int mt = 0; mt < 4; mt++)
#pragma unroll
                for (int p = 0; p < 2; p++) {
                    mma16816(acc[mt][2*p],   ah[mt][0],ah[mt][1],ah[mt][2],ah[mt][3], bl[p*4+0], bl[p*4+2]);
                    mma16816(acc[mt][2*p+1], ah[mt][0],ah[mt][1],ah[mt][2],ah[mt][3], bl[p*4+1], bl[p*4+3]);
                }
        }
        __syncthreads();
    }

    // Epilogue
#pragma unroll
    for (int mt = 0; mt < 4; mt++) {
#pragma unroll
        for (int nt = 0; nt < 4; nt++) {
            int gr = m0 + wm*64 + mt*16 + (lane >> 2);
            int gc = n0 + wn*32 + nt*8 + (lane & 3)*2;
            float b0 = bias[gc], b1 = bias[gc+1];
            float v0 = acc[mt][nt][0] + b0, v1 = acc[mt][nt][1] + b1;
            float v2 = acc[mt][nt][2] + b0, v3 = acc[mt][nt][3] + b1;
            if (outMode == 0) {
                *(float2*)(Cf + (size_t)gr*Dd + gc)     = make_float2(v0, v1);
                *(float2*)(Cf + (size_t)(gr+8)*Dd + gc) = make_float2(v2, v3);
            } else {
                Co[(size_t)gr*512 + (gc>>1)]     = pack_h(v0, v1);
                Co[(size_t)(gr+8)*512 + (gc>>1)] = pack_h(v2, v3);
            }
        }
    }
}

// ---------------------------------------------------------------------------
// Flash attention, plain fp16 (Q, K, V, P all 1-pass). CTA = 128 q-rows of
// one (b,h). 8 warps. posr fp32. K/V double-buffered.
// ---------------------------------------------------------------------------
#define AQ 0
#define AKV 16384              // stage: K 8K | V 8K
#define AKVST 16384
#define ASMEM (AKV + 2*AKVST)  // 49152

__device__ __forceinline__ void attn_load_kv(uint32_t base,
    const __half* K, const __half* V,
    size_t rowBase, int headOff, int k0, int tid)
{
#pragma unroll
    for (int i = 0; i < 2; i++) {
        int idx = tid + i * 256;          // 0..511 : 64 rows x 8 chunks
        int r = idx >> 3, c = idx & 7;
        uint32_t so = swz(r, c);
        size_t g = (rowBase + k0 + r) * Dd + headOff + c * 8;
        cp16(base + so,        K + g);
        cp16(base + 8192 + so, V + g);
    }
}

__global__ __launch_bounds__(256, 2) void attn_kernel(
    const __half* __restrict__ Q,
    const __half* __restrict__ K, const __half* __restrict__ V,
    uint32_t* __restrict__ Co,
    const float* __restrict__ posr, const int* __restrict__ mask)
{
    extern __shared__ __align__(16) char sm[];
    const uint32_t smb = smem_u32(sm);
    const int tid = threadIdx.x, wid = tid >> 5, lane = tid & 31;
    const int sub = lane >> 3, lr = lane & 7;
    const int q0 = blockIdx.x * 128;
    const int h  = blockIdx.y;
    const int b  = blockIdx.z;
    const int headOff = h * 64;
    const size_t rowBase = (size_t)b * Ss;

    // load Q tile (128 x 64 fp16)
#pragma unroll
    for (int i = 0; i < 4; i++) {
        int idx = tid + i * 256;          // 0..1023
        int r = idx >> 3, c = idx & 7;
        cp16(smb + AQ + swz(r, c), Q + (rowBase + q0 + r) * Dd + headOff + c * 8);
    }
    attn_load_kv(smb + AKV, K, V, rowBase, headOff, 0, tid);
    CP_COMMIT();
    cp_wait<0>();
    __syncthreads();

    // preload Q fragments (warp-owned rows fixed)
    uint32_t qf[4][4];
#pragma unroll
    for (int ks = 0; ks < 4; ks++) {
        int row = wid*16 + lr + (sub & 1)*8;
        int ch  = 2*ks + (sub >> 1);
        ldmx4(qf[ks][0], qf[ks][1], qf[ks][2], qf[ks][3], smb + AQ + swz(row, ch));
    }

    float o[8][4];
#pragma unroll
    for (int i = 0; i < 8; i++)
#pragma unroll
        for (int j = 0; j < 4; j++) o[i][j] = 0.f;
    float mrow[2] = {-1e30f, -1e30f};
    float lrow[2] = {0.f, 0.f};

    const int r_lo = q0 + wid*16 + (lane >> 2);
    const int r_hi = r_lo + 8;
    const float* prLo = posr + ((size_t)b*Ss + r_lo)*Ss;
    const float* prHi = posr + ((size_t)b*Ss + r_hi)*Ss;
    const int*   mkB  = mask + b*Ss;

    for (int kt = 0; kt < 32; kt++) {
        uint32_t stg = smb + AKV + (kt & 1) * AKVST;
        if (kt + 1 < 32) {
            attn_load_kv(smb + AKV + ((kt+1) & 1) * AKVST, K, V,
                         rowBase, headOff, (kt+1)*64, tid);
            CP_COMMIT();
            cp_wait<1>();
        } else {
            cp_wait<0>();
        }
        __syncthreads();

        // ---- S = Q @ K^T (plain fp16) ----
        float s[8][4];
#pragma unroll
        for (int i = 0; i < 8; i++)
#pragma unroll
            for (int j = 0; j < 4; j++) s[i][j] = 0.f;

#pragma unroll
        for (int ks = 0; ks < 4; ks++) {
#pragma unroll
            for (int p = 0; p < 4; p++) {    // pairs of n-tiles (2p, 2p+1)
                int row = p*16 + lr + (sub & 1)*8;
                int ch  = 2*ks + (sub >> 1);
                uint32_t kh4[4];
                ldmx4(kh4[0], kh4[1], kh4[2], kh4[3], stg + swz(row, ch));
                mma16816(s[2*p],   qf[ks][0],qf[ks][1],qf[ks][2],qf[ks][3], kh4[0], kh4[2]);
                mma16816(s[2*p+1], qf[ks][0],qf[ks][1],qf[ks][2],qf[ks][3], kh4[1], kh4[3]);
            }
        }

        // ---- scale + posr(fp32) + mask ----
        const int colB = kt*64 + (lane & 3)*2;
#pragma unroll
        for (int nt = 0; nt < 8; nt++) {
            int col = colB + nt*8;
            int2 mk = *(const int2*)(mkB + col);
            float2 p0 = *(const float2*)(prLo + col);
            float2 p1 = *(const float2*)(prHi + col);
            s[nt][0] = (mk.x != 0) ? fmaf(s[nt][0], 0.125f, p0.x) : -1e9f;
            s[nt][1] = (mk.y != 0) ? fmaf(s[nt][1], 0.125f, p0.y) : -1e9f;
            s[nt][2] = (mk.x != 0) ? fmaf(s[nt][2], 0.125f, p1.x) : -1e9f;
            s[nt][3] = (mk.y != 0) ? fmaf(s[nt][3], 0.125f, p1.y) : -1e9f;
        }

        // ---- online softmax ----
        float tm0 = -1e30f, tm1 = -1e30f;
#pragma unroll
        for (int nt = 0; nt < 8; nt++) {
            tm0 = fmaxf(tm0, fmaxf(s[nt][0], s[nt][1]));
            tm1 = fmaxf(tm1, fmaxf(s[nt][2], s[nt][3]));
        }
        tm0 = fmaxf(tm0, __shfl_xor_sync(0xffffffffu, tm0, 1));
        tm0 = fmaxf(tm0, __shfl_xor_sync(0xffffffffu, tm0, 2));
        tm1 = fmaxf(tm1, __shfl_xor_sync(0xffffffffu, tm1, 1));
        tm1 = fmaxf(tm1, __shfl_xor_sync(0xffffffffu, tm1, 2));

        float mn0 = fmaxf(mrow[0], tm0), mn1 = fmaxf(mrow[1], tm1);
        float f0 = fast_exp(mrow[0] - mn0), f1 = fast_exp(mrow[1] - mn1);
        mrow[0] = mn0; mrow[1] = mn1;

        float sum0 = 0.f, sum1 = 0.f;
#pragma unroll
        for (int nt = 0; nt < 8; nt++) {
            s[nt][0] = fast_exp(s[nt][0] - mn0);
            s[nt][1] = fast_exp(s[nt][1] - mn0);
            s[nt][2] = fast_exp(s[nt][2] - mn1);
            s[nt][3] = fast_exp(s[nt][3] - mn1);
            sum0 += s[nt][0] + s[nt][1];
            sum1 += s[nt][2] + s[nt][3];
        }
        sum0 += __shfl_xor_sync(0xffffffffu, sum0, 1);
        sum0 += __shfl_xor_sync(0xffffffffu, sum0, 2);
        sum1 += __shfl_xor_sync(0xffffffffu, sum1, 1);
        sum1 += __shfl_xor_sync(0xffffffffu, sum1, 2);
        lrow[0] = lrow[0] * f0 + sum0;
        lrow[1] = lrow[1] * f1 + sum1;

#pragma unroll
        for (int nt2 = 0; nt2 < 8; nt2++) {
            o[nt2][0] *= f0; o[nt2][1] *= f0;
            o[nt2][2] *= f1; o[nt2][3] *= f1;
        }

        // ---- pack P (plain fp16) into A-frags; acc += P @ V ----
#pragma unroll
        for (int ks = 0; ks < 4; ks++) {
            int t0 = 2*ks, t1 = 2*ks + 1;
            uint32_t ph0 = pack_h(s[t0][0], s[t0][1]);
            uint32_t ph1 = pack_h(s[t0][2], s[t0][3]);
            uint32_t ph2 = pack_h(s[t1][0], s[t1][1]);
            uint32_t ph3 = pack_h(s[t1][2], s[t1][3]);
            int row = ks*16 + (lane & 15);
#pragma unroll
            for (int np = 0; np < 4; np++) {   // pairs of d-tiles (2np, 2np+1)
                uint32_t so = swz(row, np*2 + (lane >> 4));
                uint32_t h0,h1,h2,h3;
                ldmx4t(h0,h1,h2,h3, stg + 8192 + so);
                mma16816(o[2*np],   ph0,ph1,ph2,ph3, h0,h1);
                mma16816(o[2*np+1], ph0,ph1,ph2,ph3, h2,h3);
            }
        }
        __syncthreads();
    }

    // ---- epilogue: normalize, write ctx (plain fp16) ----
    float inv0 = 1.f / lrow[0], inv1 = 1.f / lrow[1];
    const size_t grLo = rowBase + (size_t)r_lo;
    const size_t grHi = rowBase + (size_t)r_hi;
#pragma unroll
    for (int nt2 = 0; nt2 < 8; nt2++) {
        int gc = headOff + nt2*8 + (lane & 3)*2;
        Co[grLo*512 + (gc>>1)] = pack_h(o[nt2][0] * inv0, o[nt2][1] * inv0);
        Co[grHi*512 + (gc>>1)] = pack_h(o[nt2][2] * inv1, o[nt2][3] * inv1);
    }
}

// ---------------------------------------------------------------------------
extern "C" void kernel_launch(void* const* d_in, const int* in_sizes, int n_in,
                              void* d_out, int out_size)
{
    const float* query = (const float*)d_in[0];
    const float* key   = (const float*)d_in[1];
    const float* value = (const float*)d_in[2];
    const int*   mask  = (const int*)  d_in[3];
    const float* posr  = (const float*)d_in[4];
    const float* Wq    = (const float*)d_in[5];
    const float* bq    = (const float*)d_in[6];
    const float* Wk    = (const float*)d_in[7];
    const float* bk    = (const float*)d_in[8];
    const float* Wv    = (const float*)d_in[9];
    const float* bv    = (const float*)d_in[10];
    const float* Wo    = (const float*)d_in[11];
    const float* bo    = (const float*)d_in[12];
    float* out = (float*)d_out;

    __half *xq,*xk,*xv, *q16,*k16,*v16, *c16;
    __half *wqh,*wql,*wkh,*wkl,*wvh,*wvl,*woh,*wol;
    cudaGetSymbolAddress((void**)&xq, g_xq);   cudaGetSymbolAddress((void**)&xk, g_xk);
    cudaGetSymbolAddress((void**)&xv, g_xv);
    cudaGetSymbolAddress((void**)&wqh, g_wqh); cudaGetSymbolAddress((void**)&wql, g_wql);
    cudaGetSymbolAddress((void**)&wkh, g_wkh); cudaGetSymbolAddress((void**)&wkl, g_wkl);
    cudaGetSymbolAddress((void**)&wvh, g_wvh); cudaGetSymbolAddress((void**)&wvl, g_wvl);
    cudaGetSymbolAddress((void**)&woh, g_woh); cudaGetSymbolAddress((void**)&wol, g_wol);
    cudaGetSymbolAddress((void**)&q16, g_q);   cudaGetSymbolAddress((void**)&k16, g_k);
    cudaGetSymbolAddress((void**)&v16, g_v);
    cudaGetSymbolAddress((void**)&c16, g_c);

    pre_cvt3<<<dim3(Mm, 3), 256>>>((const float4*)query, (const float4*)key, (const float4*)value,
        (uint32_t*)xq, (uint32_t*)xk, (uint32_t*)xv);
    pre_split4<<<dim3(Dd, 4), 256>>>((const float4*)Wq, (const float4*)Wk, (const float4*)Wv, (const float4*)Wo,
        (uint32_t*)wqh, (uint32_t*)wql, (uint32_t*)wkh, (uint32_t*)wkl,
        (uint32_t*)wvh, (uint32_t*)wvl, (uint32_t*)woh, (uint32_t*)wol);

    cudaFuncSetAttribute(gemm_f16x2, cudaFuncAttributeMaxDynamicSharedMemorySize, GSMEM);
    cudaFuncSetAttribute(attn_kernel, cudaFuncAttributeMaxDynamicSharedMemorySize, ASMEM);

    dim3 gGrid(Dd/128, Mm/256);   // (8, 16) = 128 CTAs
    gemm_f16x2<<<gGrid, 512, GSMEM>>>(xq, wqh, wql, bq, nullptr, (uint32_t*)q16, 1);
    gemm_f16x2<<<gGrid, 512, GSMEM>>>(xk, wkh, wkl, bk, nullptr, (uint32_t*)k16, 1);
    gemm_f16x2<<<gGrid, 512, GSMEM>>>(xv, wvh, wvl, bv, nullptr, (uint32_t*)v16, 1);

    // launch #6 (ncu -s 5 -c 1 captures this one)
    attn_kernel<<<dim3(Ss/128, Hh, Bb), 256, ASMEM>>>(q16, k16, v16,
        (uint32_t*)c16, posr, mask);

    gemm_f16x2<<<gGrid, 512, GSMEM>>>(c16, woh, wol, bo, out, nullptr, 0);
}